// round 3
// baseline (speedup 1.0000x reference)
#include <cuda_runtime.h>
#include <math.h>
#include <stdint.h>

// Problem-fixed shapes: N=100000, C=256, H=128, K=64, E=1600000
#define NN   100000
#define EE   1600000
#define ETOT (EE + NN)
#define CDIM 256
#define HDIM 128
#define KOUT 64

// ---------------- device scratch (static, no allocation) ----------------
__device__ int   g_deg[NN];
__device__ int   g_incl[NN];
__device__ int   g_bsums[256];
__device__ int   g_rowptr[NN + 1];
__device__ int   g_pos[NN];
__device__ int   g_col[ETOT];
__device__ float g_h1[NN * HDIM];
__device__ float g_x1[NN * HDIM];
__device__ float g_h2[NN * KOUT];
__device__ float g_s1[NN], g_d1[NN], g_s2[NN], g_d2[NN];

// ---------------- CSR build ----------------
__global__ void init_deg_kernel(int* deg, int n) {
    int i = blockIdx.x * blockDim.x + threadIdx.x;
    if (i < n) deg[i] = 1;  // self-loop
}

__global__ void hist_kernel(const int* __restrict__ dst, int* deg, int e) {
    int i = blockIdx.x * blockDim.x + threadIdx.x;
    if (i < e) atomicAdd(&deg[dst[i]], 1);
}

__global__ void scan_block_kernel(const int* __restrict__ deg, int* incl, int* bsums, int n) {
    __shared__ int sh[1024];
    int t = threadIdx.x;
    int gid = blockIdx.x * 1024 + t;
    sh[t] = (gid < n) ? deg[gid] : 0;
    __syncthreads();
    #pragma unroll
    for (int off = 1; off < 1024; off <<= 1) {
        int v = (t >= off) ? sh[t - off] : 0;
        __syncthreads();
        sh[t] += v;
        __syncthreads();
    }
    if (gid < n) incl[gid] = sh[t];
    if (t == 1023) bsums[blockIdx.x] = sh[t];
}

// parallel exclusive scan of block sums (nb <= 128)
__global__ void scan_bsums_kernel(int* bsums, int nb) {
    __shared__ int sh[128];
    int t = threadIdx.x;
    sh[t] = (t < nb) ? bsums[t] : 0;
    __syncthreads();
    #pragma unroll
    for (int off = 1; off < 128; off <<= 1) {
        int v = (t >= off) ? sh[t - off] : 0;
        __syncthreads();
        sh[t] += v;
        __syncthreads();
    }
    if (t < nb) bsums[t] = (t == 0) ? 0 : sh[t - 1];
}

// rowptr[i+1] = inclusive csum; also pos[i] = rowptr[i] (fused copy_pos)
__global__ void finalize_rowptr_kernel(const int* __restrict__ incl, const int* __restrict__ bsums,
                                       const int* __restrict__ deg, int* rowptr, int* pos, int n) {
    int gid = blockIdx.x * blockDim.x + threadIdx.x;
    if (gid < n) {
        int v = incl[gid] + bsums[gid >> 10];
        rowptr[gid + 1] = v;
        pos[gid] = v - deg[gid];
    }
    if (gid == 0) rowptr[0] = 0;
}

__global__ void scatter_kernel(const int* __restrict__ srcv, const int* __restrict__ dstv,
                               int* pos, int* colv, int e) {
    int i = blockIdx.x * blockDim.x + threadIdx.x;
    if (i < e) {
        int p = atomicAdd(&pos[dstv[i]], 1);
        colv[p] = srcv[i];
    }
}

__global__ void selfloop_kernel(int* pos, int* colv, int n) {
    int i = blockIdx.x * blockDim.x + threadIdx.x;
    if (i < n) {
        int p = atomicAdd(&pos[i], 1);
        colv[p] = i;
    }
}

// ---------------- tf32 tensor-core GEMM + fused attention dots ----------------
// C[M x BN] = A[M x KD] * B[KD x BN]; also sv[i]=C[i,:].asrc, dv[i]=C[i,:].adst
__device__ __forceinline__ uint32_t f2tf32(float f) {
    uint32_t r;
    asm("cvt.rna.tf32.f32 %0, %1;" : "=r"(r) : "f"(f));
    return r;
}

template <int BN, int KD>
__global__ __launch_bounds__(256) void mma_gemm_kernel(const float* __restrict__ A,
                                                       const float* __restrict__ B,
                                                       float* __restrict__ Cmat,
                                                       const float* __restrict__ asrc,
                                                       const float* __restrict__ adst,
                                                       float* __restrict__ sv,
                                                       float* __restrict__ dv, int M) {
    constexpr int BM = 128, BK = 32;
    constexpr int WN = BN / 4;
    constexpr int MT = 4;
    constexpr int NT = WN / 8;
    constexpr int AST = BK + 4;
    constexpr int BST = BN + 8;

    __shared__ float As[BM][AST];
    __shared__ float Bs[BK][BST];
    __shared__ float sred[2][BM];

    int tid = threadIdx.x;
    int lane = tid & 31;
    int wid = tid >> 5;
    int wm = wid & 1;
    int wn = wid >> 1;
    int rowBase = blockIdx.x * BM;

    float acc[MT][NT][4];
    #pragma unroll
    for (int i = 0; i < MT; i++)
        #pragma unroll
        for (int j = 0; j < NT; j++)
            #pragma unroll
            for (int r = 0; r < 4; r++) acc[i][j][r] = 0.f;

    for (int k0 = 0; k0 < KD; k0 += BK) {
        #pragma unroll
        for (int it = 0; it < 4; it++) {
            int idx = tid + 256 * it;
            int row = idx >> 3;
            int q = idx & 7;
            float4 v = make_float4(0.f, 0.f, 0.f, 0.f);
            int gr = rowBase + row;
            if (gr < M) v = *reinterpret_cast<const float4*>(A + (size_t)gr * KD + k0 + 4 * q);
            float4 w;
            w.x = __uint_as_float(f2tf32(v.x));
            w.y = __uint_as_float(f2tf32(v.y));
            w.z = __uint_as_float(f2tf32(v.z));
            w.w = __uint_as_float(f2tf32(v.w));
            *reinterpret_cast<float4*>(&As[row][4 * q]) = w;
        }
        constexpr int BQ = BN / 4;
        constexpr int BIT = (BK * BQ) / 256;
        #pragma unroll
        for (int it = 0; it < BIT; it++) {
            int idx = tid + 256 * it;
            int row = idx / BQ;
            int q = idx % BQ;
            float4 v = *reinterpret_cast<const float4*>(B + (size_t)(k0 + row) * BN + 4 * q);
            float4 w;
            w.x = __uint_as_float(f2tf32(v.x));
            w.y = __uint_as_float(f2tf32(v.y));
            w.z = __uint_as_float(f2tf32(v.z));
            w.w = __uint_as_float(f2tf32(v.w));
            *reinterpret_cast<float4*>(&Bs[row][4 * q]) = w;
        }
        __syncthreads();

        #pragma unroll
        for (int kk = 0; kk < BK / 8; kk++) {
            uint32_t af[MT][4];
            #pragma unroll
            for (int mt = 0; mt < MT; mt++) {
                int r0 = wm * 64 + mt * 16 + (lane >> 2);
                int c0 = 8 * kk + (lane & 3);
                af[mt][0] = __float_as_uint(As[r0][c0]);
                af[mt][1] = __float_as_uint(As[r0 + 8][c0]);
                af[mt][2] = __float_as_uint(As[r0][c0 + 4]);
                af[mt][3] = __float_as_uint(As[r0 + 8][c0 + 4]);
            }
            uint32_t bf[NT][2];
            #pragma unroll
            for (int nt = 0; nt < NT; nt++) {
                int col = wn * WN + nt * 8 + (lane >> 2);
                int kr = 8 * kk + (lane & 3);
                bf[nt][0] = __float_as_uint(Bs[kr][col]);
                bf[nt][1] = __float_as_uint(Bs[kr + 4][col]);
            }
            #pragma unroll
            for (int mt = 0; mt < MT; mt++)
                #pragma unroll
                for (int nt = 0; nt < NT; nt++) {
                    asm volatile(
                        "mma.sync.aligned.m16n8k8.row.col.f32.tf32.tf32.f32 "
                        "{%0,%1,%2,%3}, {%4,%5,%6,%7}, {%8,%9}, {%0,%1,%2,%3};"
                        : "+f"(acc[mt][nt][0]), "+f"(acc[mt][nt][1]),
                          "+f"(acc[mt][nt][2]), "+f"(acc[mt][nt][3])
                        : "r"(af[mt][0]), "r"(af[mt][1]), "r"(af[mt][2]), "r"(af[mt][3]),
                          "r"(bf[nt][0]), "r"(bf[nt][1]));
                }
        }
        __syncthreads();
    }

    // zero dot-reduction buffer
    for (int t = tid; t < 2 * BM; t += 256) (&sred[0][0])[t] = 0.f;
    __syncthreads();

    // C stores + per-warp dot partials
    #pragma unroll
    for (int mt = 0; mt < MT; mt++) {
        int rl = wm * 64 + mt * 16 + (lane >> 2);
        int r0 = rowBase + rl;
        float s_lo = 0.f, d_lo = 0.f, s_hi = 0.f, d_hi = 0.f;
        #pragma unroll
        for (int nt = 0; nt < NT; nt++) {
            int col = wn * WN + nt * 8 + 2 * (lane & 3);
            float a0 = asrc[col], a1 = asrc[col + 1];
            float e0 = adst[col], e1 = adst[col + 1];
            s_lo += acc[mt][nt][0] * a0 + acc[mt][nt][1] * a1;
            d_lo += acc[mt][nt][0] * e0 + acc[mt][nt][1] * e1;
            s_hi += acc[mt][nt][2] * a0 + acc[mt][nt][3] * a1;
            d_hi += acc[mt][nt][2] * e0 + acc[mt][nt][3] * e1;
            if (r0 < M)
                *reinterpret_cast<float2*>(Cmat + (size_t)r0 * BN + col) =
                    make_float2(acc[mt][nt][0], acc[mt][nt][1]);
            if (r0 + 8 < M)
                *reinterpret_cast<float2*>(Cmat + (size_t)(r0 + 8) * BN + col) =
                    make_float2(acc[mt][nt][2], acc[mt][nt][3]);
        }
        // reduce within quad (lanes sharing same row)
        #pragma unroll
        for (int o = 1; o <= 2; o <<= 1) {
            s_lo += __shfl_xor_sync(0xffffffffu, s_lo, o);
            d_lo += __shfl_xor_sync(0xffffffffu, d_lo, o);
            s_hi += __shfl_xor_sync(0xffffffffu, s_hi, o);
            d_hi += __shfl_xor_sync(0xffffffffu, d_hi, o);
        }
        if ((lane & 3) == 0) {
            atomicAdd(&sred[0][rl], s_lo);
            atomicAdd(&sred[1][rl], d_lo);
            atomicAdd(&sred[0][rl + 8], s_hi);
            atomicAdd(&sred[1][rl + 8], d_hi);
        }
    }
    __syncthreads();
    for (int t = tid; t < BM; t += 256) {
        int gr = rowBase + t;
        if (gr < M) { sv[gr] = sred[0][t]; dv[gr] = sred[1][t]; }
    }
}

// ---------------- aggregation: out[i] = act( softmax-weighted sum + b ) ----------------
// F=128 -> float4/lane; F=64 -> float2/lane. ACT: 0=relu, 1=sigmoid
template <int F, int ACT>
__global__ __launch_bounds__(256) void aggregate_kernel(
        const float* __restrict__ h, const float* __restrict__ sv,
        const float* __restrict__ dv, const int* __restrict__ rowptr,
        const int* __restrict__ colidx, const float* __restrict__ bias,
        float* __restrict__ out, int n) {
    constexpr int V = F / 32;  // floats per lane
    int warp = (blockIdx.x * blockDim.x + threadIdx.x) >> 5;
    int lane = threadIdx.x & 31;
    if (warp >= n) return;
    int i = warp;
    int start = rowptr[i], end = rowptr[i + 1];
    float di = dv[i];

    // pass 1: max logit
    float m = -INFINITY;
    for (int j = start + lane; j < end; j += 32) {
        float x = sv[colidx[j]] + di;
        x = (x > 0.f) ? x : 0.2f * x;
        m = fmaxf(m, x);
    }
    #pragma unroll
    for (int o = 16; o; o >>= 1) m = fmaxf(m, __shfl_xor_sync(0xffffffffu, m, o));

    float acc[V];
    #pragma unroll
    for (int f = 0; f < V; f++) acc[f] = 0.f;
    float Z = 0.f;

    for (int j0 = start; j0 < end; j0 += 32) {
        int j = j0 + lane;
        int sn = 0;
        float w = 0.f;
        if (j < end) {
            sn = colidx[j];
            float x = sv[sn] + di;
            x = (x > 0.f) ? x : 0.2f * x;
            w = __expf(x - m);
            Z += w;
        }
        int cnt = min(32, end - j0);
        int t = 0;
        for (; t + 4 <= cnt; t += 4) {
            int s0 = __shfl_sync(0xffffffffu, sn, t);
            int s1 = __shfl_sync(0xffffffffu, sn, t + 1);
            int s2 = __shfl_sync(0xffffffffu, sn, t + 2);
            int s3 = __shfl_sync(0xffffffffu, sn, t + 3);
            float w0 = __shfl_sync(0xffffffffu, w, t);
            float w1 = __shfl_sync(0xffffffffu, w, t + 1);
            float w2 = __shfl_sync(0xffffffffu, w, t + 2);
            float w3 = __shfl_sync(0xffffffffu, w, t + 3);
            float v0[V], v1[V], v2[V], v3[V];
            #pragma unroll
            for (int f = 0; f < V; f++) v0[f] = h[(size_t)s0 * F + V * lane + f];
            #pragma unroll
            for (int f = 0; f < V; f++) v1[f] = h[(size_t)s1 * F + V * lane + f];
            #pragma unroll
            for (int f = 0; f < V; f++) v2[f] = h[(size_t)s2 * F + V * lane + f];
            #pragma unroll
            for (int f = 0; f < V; f++) v3[f] = h[(size_t)s3 * F + V * lane + f];
            #pragma unroll
            for (int f = 0; f < V; f++)
                acc[f] += w0 * v0[f] + w1 * v1[f] + w2 * v2[f] + w3 * v3[f];
        }
        for (; t < cnt; t++) {
            int sb = __shfl_sync(0xffffffffu, sn, t);
            float wb = __shfl_sync(0xffffffffu, w, t);
            #pragma unroll
            for (int f = 0; f < V; f++)
                acc[f] += wb * h[(size_t)sb * F + V * lane + f];
        }
    }
    #pragma unroll
    for (int o = 16; o; o >>= 1) Z += __shfl_xor_sync(0xffffffffu, Z, o);
    float invZ = 1.f / (Z + 1e-16f);
    #pragma unroll
    for (int f = 0; f < V; f++) {
        float v = acc[f] * invZ + bias[V * lane + f];
        if (ACT == 0) v = fmaxf(v, 0.f);
        else          v = 1.f / (1.f + __expf(-v));
        acc[f] = v;
    }
    if (V == 4)
        *reinterpret_cast<float4*>(out + (size_t)i * F + 4 * lane) =
            make_float4(acc[0], acc[1], acc[2], acc[V - 1]);
    else
        *reinterpret_cast<float2*>(out + (size_t)i * F + 2 * lane) =
            make_float2(acc[0], acc[V - 1]);
}

// ---------------- host launch ----------------
static inline int cdiv(int a, int b) { return (a + b - 1) / b; }

extern "C" void kernel_launch(void* const* d_in, const int* in_sizes, int n_in,
                              void* d_out, int out_size) {
    const int*   ei    = (const int*)d_in[0];
    const float* embed = (const float*)d_in[1];
    const float* W1    = (const float*)d_in[2];
    const float* as1   = (const float*)d_in[3];
    const float* ad1   = (const float*)d_in[4];
    const float* b1    = (const float*)d_in[5];
    const float* W2    = (const float*)d_in[6];
    const float* as2   = (const float*)d_in[7];
    const float* ad2   = (const float*)d_in[8];
    const float* b2    = (const float*)d_in[9];

    int E = in_sizes[0] / 2;
    int N = in_sizes[1] / CDIM;
    const int* srcv = ei;
    const int* dstv = ei + E;

    void* p;
    cudaGetSymbolAddress(&p, g_deg);    int* deg    = (int*)p;
    cudaGetSymbolAddress(&p, g_incl);   int* incl   = (int*)p;
    cudaGetSymbolAddress(&p, g_bsums);  int* bsums  = (int*)p;
    cudaGetSymbolAddress(&p, g_rowptr); int* rowptr = (int*)p;
    cudaGetSymbolAddress(&p, g_pos);    int* pos    = (int*)p;
    cudaGetSymbolAddress(&p, g_col);    int* col    = (int*)p;
    cudaGetSymbolAddress(&p, g_h1);     float* h1   = (float*)p;
    cudaGetSymbolAddress(&p, g_x1);     float* x1   = (float*)p;
    cudaGetSymbolAddress(&p, g_h2);     float* h2   = (float*)p;
    cudaGetSymbolAddress(&p, g_s1);     float* s1   = (float*)p;
    cudaGetSymbolAddress(&p, g_d1);     float* d1   = (float*)p;
    cudaGetSymbolAddress(&p, g_s2);     float* s2   = (float*)p;
    cudaGetSymbolAddress(&p, g_d2);     float* d2   = (float*)p;
    float* out = (float*)d_out;

    int nb = cdiv(N, 1024);

    // CSR build interleaved with independent GEMM1 (GEMM1 placed 4th for ncu window)
    init_deg_kernel<<<cdiv(N, 256), 256>>>(deg, N);
    hist_kernel<<<cdiv(E, 256), 256>>>(dstv, deg, E);
    scan_block_kernel<<<nb, 1024>>>(deg, incl, bsums, N);
    mma_gemm_kernel<HDIM, CDIM><<<cdiv(N, 128), 256>>>(embed, W1, h1, as1, ad1, s1, d1, N);
    scan_bsums_kernel<<<1, 128>>>(bsums, nb);
    finalize_rowptr_kernel<<<cdiv(N + 1, 256), 256>>>(incl, bsums, deg, rowptr, pos, N);
    scatter_kernel<<<cdiv(E, 256), 256>>>(srcv, dstv, pos, col, E);
    selfloop_kernel<<<cdiv(N, 256), 256>>>(pos, col, N);

    // Layer 1 aggregation
    aggregate_kernel<HDIM, 0><<<cdiv(N, 8), 256>>>(h1, s1, d1, rowptr, col, b1, x1, N);

    // Layer 2
    mma_gemm_kernel<KOUT, HDIM><<<cdiv(N, 128), 256>>>(x1, W2, h2, as2, ad2, s2, d2, N);
    aggregate_kernel<KOUT, 1><<<cdiv(N, 8), 256>>>(h2, s2, d2, rowptr, col, b2, out, N);
}

// round 4
// speedup vs baseline: 1.3304x; 1.3304x over previous
#include <cuda_runtime.h>
#include <math.h>
#include <stdint.h>

// Problem-fixed shapes: N=100000, C=256, H=128, K=64, E=1600000
#define NN   100000
#define EE   1600000
#define ETOT (EE + NN)
#define CDIM 256
#define HDIM 128
#define KOUT 64

// ---------------- device scratch (static, no allocation) ----------------
__device__ int   g_deg[NN];
__device__ int   g_incl[NN];
__device__ int   g_bsums[256];
__device__ int   g_rowptr[NN + 1];
__device__ int   g_pos[NN];
__device__ int   g_col[ETOT];
__device__ float g_h1[NN * HDIM];
__device__ float g_x1[NN * HDIM];
__device__ float g_h2[NN * KOUT];
__device__ float g_s1[NN], g_d1[NN], g_s2[NN], g_d2[NN];

// ---------------- CSR build ----------------
__global__ void init_deg_kernel(int* deg, int n) {
    int i = blockIdx.x * blockDim.x + threadIdx.x;
    if (i < n) deg[i] = 1;  // self-loop
}

__global__ void hist_kernel(const int* __restrict__ dst, int* deg, int e) {
    int i = blockIdx.x * blockDim.x + threadIdx.x;
    if (i < e) atomicAdd(&deg[dst[i]], 1);
}

__global__ void scan_block_kernel(const int* __restrict__ deg, int* incl, int* bsums, int n) {
    __shared__ int sh[1024];
    int t = threadIdx.x;
    int gid = blockIdx.x * 1024 + t;
    sh[t] = (gid < n) ? deg[gid] : 0;
    __syncthreads();
    #pragma unroll
    for (int off = 1; off < 1024; off <<= 1) {
        int v = (t >= off) ? sh[t - off] : 0;
        __syncthreads();
        sh[t] += v;
        __syncthreads();
    }
    if (gid < n) incl[gid] = sh[t];
    if (t == 1023) bsums[blockIdx.x] = sh[t];
}

__global__ void scan_bsums_kernel(int* bsums, int nb) {
    __shared__ int sh[128];
    int t = threadIdx.x;
    sh[t] = (t < nb) ? bsums[t] : 0;
    __syncthreads();
    #pragma unroll
    for (int off = 1; off < 128; off <<= 1) {
        int v = (t >= off) ? sh[t - off] : 0;
        __syncthreads();
        sh[t] += v;
        __syncthreads();
    }
    if (t < nb) bsums[t] = (t == 0) ? 0 : sh[t - 1];
}

__global__ void finalize_rowptr_kernel(const int* __restrict__ incl, const int* __restrict__ bsums,
                                       const int* __restrict__ deg, int* rowptr, int* pos, int n) {
    int gid = blockIdx.x * blockDim.x + threadIdx.x;
    if (gid < n) {
        int v = incl[gid] + bsums[gid >> 10];
        rowptr[gid + 1] = v;
        pos[gid] = v - deg[gid];
    }
    if (gid == 0) rowptr[0] = 0;
}

__global__ void scatter_kernel(const int* __restrict__ srcv, const int* __restrict__ dstv,
                               int* pos, int* colv, int e) {
    int i = blockIdx.x * blockDim.x + threadIdx.x;
    if (i < e) {
        int p = atomicAdd(&pos[dstv[i]], 1);
        colv[p] = srcv[i];
    }
}

__global__ void selfloop_kernel(int* pos, int* colv, int n) {
    int i = blockIdx.x * blockDim.x + threadIdx.x;
    if (i < n) {
        int p = atomicAdd(&pos[i], 1);
        colv[p] = i;
    }
}

// ---------------- cp.async helpers ----------------
__device__ __forceinline__ void cp_async16(void* smem_dst, const void* gmem_src, bool pred) {
    uint32_t saddr = (uint32_t)__cvta_generic_to_shared(smem_dst);
    int sz = pred ? 16 : 0;
    asm volatile("cp.async.cg.shared.global [%0], [%1], 16, %2;\n"
                 :: "r"(saddr), "l"(gmem_src), "r"(sz));
}
__device__ __forceinline__ void cp_commit() {
    asm volatile("cp.async.commit_group;\n");
}
template <int N>
__device__ __forceinline__ void cp_wait() {
    asm volatile("cp.async.wait_group %0;\n" :: "n"(N));
}

// ---------------- tf32 tensor-core GEMM, 2-stage cp.async pipeline ----------------
// C[M x BN] = A[M x KD] * B[KD x BN]; fused: sv[i]=C[i,:].asrc, dv[i]=C[i,:].adst
// f32 bits fed directly to mma.tf32 (hw truncation) — no convert pass.
template <int BN, int KD>
__global__ __launch_bounds__(256) void mma_gemm_kernel(const float* __restrict__ A,
                                                       const float* __restrict__ B,
                                                       float* __restrict__ Cmat,
                                                       const float* __restrict__ asrc,
                                                       const float* __restrict__ adst,
                                                       float* __restrict__ sv,
                                                       float* __restrict__ dv, int M) {
    constexpr int BM = 128, BK = 32;
    constexpr int WN = BN / 4;
    constexpr int MT = 4;
    constexpr int NT = WN / 8;
    constexpr int AST = BK + 4;     // 36: a-frag scalar reads conflict-free
    constexpr int BST = BN + 8;     // b-frag scalar reads conflict-free
    constexpr int T = KD / BK;

    extern __shared__ float smem[];
    float* AsBase = smem;                     // [2][BM][AST]
    float* BsBase = smem + 2 * BM * AST;      // [2][BK][BST]

    int tid = threadIdx.x;
    int lane = tid & 31;
    int wid = tid >> 5;
    int wm = wid & 1;
    int wn = wid >> 1;
    int rowBase = blockIdx.x * BM;

    float acc[MT][NT][4];
    #pragma unroll
    for (int i = 0; i < MT; i++)
        #pragma unroll
        for (int j = 0; j < NT; j++)
            #pragma unroll
            for (int r = 0; r < 4; r++) acc[i][j][r] = 0.f;

    auto loadTiles = [&](int stage, int k0) {
        float* As = AsBase + stage * BM * AST;
        float* Bs = BsBase + stage * BK * BST;
        #pragma unroll
        for (int it = 0; it < 4; it++) {
            int idx = tid + 256 * it;
            int row = idx >> 3;
            int q = idx & 7;
            int gr = rowBase + row;
            cp_async16(As + row * AST + 4 * q,
                       A + (size_t)gr * KD + k0 + 4 * q, gr < M);
        }
        constexpr int BQ = BN / 4;
        constexpr int BIT = (BK * BQ) / 256;
        #pragma unroll
        for (int it = 0; it < BIT; it++) {
            int idx = tid + 256 * it;
            int row = idx / BQ;
            int q = idx % BQ;
            cp_async16(Bs + row * BST + 4 * q,
                       B + (size_t)(k0 + row) * BN + 4 * q, true);
        }
        cp_commit();
    };

    loadTiles(0, 0);

    for (int t = 0; t < T; t++) {
        int st = t & 1;
        if (t + 1 < T) {
            loadTiles((t + 1) & 1, (t + 1) * BK);
            cp_wait<1>();
        } else {
            cp_wait<0>();
        }
        __syncthreads();

        const float* As = AsBase + st * BM * AST;
        const float* Bs = BsBase + st * BK * BST;
        #pragma unroll
        for (int kk = 0; kk < BK / 8; kk++) {
            uint32_t af[MT][4];
            #pragma unroll
            for (int mt = 0; mt < MT; mt++) {
                int r0 = wm * 64 + mt * 16 + (lane >> 2);
                int c0 = 8 * kk + (lane & 3);
                af[mt][0] = __float_as_uint(As[r0 * AST + c0]);
                af[mt][1] = __float_as_uint(As[(r0 + 8) * AST + c0]);
                af[mt][2] = __float_as_uint(As[r0 * AST + c0 + 4]);
                af[mt][3] = __float_as_uint(As[(r0 + 8) * AST + c0 + 4]);
            }
            uint32_t bf[NT][2];
            #pragma unroll
            for (int nt = 0; nt < NT; nt++) {
                int col = wn * WN + nt * 8 + (lane >> 2);
                int kr = 8 * kk + (lane & 3);
                bf[nt][0] = __float_as_uint(Bs[kr * BST + col]);
                bf[nt][1] = __float_as_uint(Bs[(kr + 4) * BST + col]);
            }
            #pragma unroll
            for (int mt = 0; mt < MT; mt++)
                #pragma unroll
                for (int nt = 0; nt < NT; nt++) {
                    asm volatile(
                        "mma.sync.aligned.m16n8k8.row.col.f32.tf32.tf32.f32 "
                        "{%0,%1,%2,%3}, {%4,%5,%6,%7}, {%8,%9}, {%0,%1,%2,%3};"
                        : "+f"(acc[mt][nt][0]), "+f"(acc[mt][nt][1]),
                          "+f"(acc[mt][nt][2]), "+f"(acc[mt][nt][3])
                        : "r"(af[mt][0]), "r"(af[mt][1]), "r"(af[mt][2]), "r"(af[mt][3]),
                          "r"(bf[nt][0]), "r"(bf[nt][1]));
                }
        }
        __syncthreads();
    }

    // epilogue: overlay dot-reduction buffer on (now free) smem
    float* sred = smem;  // [2][BM]
    for (int t = tid; t < 2 * BM; t += 256) sred[t] = 0.f;
    __syncthreads();

    #pragma unroll
    for (int mt = 0; mt < MT; mt++) {
        int rl = wm * 64 + mt * 16 + (lane >> 2);
        int r0 = rowBase + rl;
        float s_lo = 0.f, d_lo = 0.f, s_hi = 0.f, d_hi = 0.f;
        #pragma unroll
        for (int nt = 0; nt < NT; nt++) {
            int col = wn * WN + nt * 8 + 2 * (lane & 3);
            float a0 = asrc[col], a1 = asrc[col + 1];
            float e0 = adst[col], e1 = adst[col + 1];
            s_lo += acc[mt][nt][0] * a0 + acc[mt][nt][1] * a1;
            d_lo += acc[mt][nt][0] * e0 + acc[mt][nt][1] * e1;
            s_hi += acc[mt][nt][2] * a0 + acc[mt][nt][3] * a1;
            d_hi += acc[mt][nt][2] * e0 + acc[mt][nt][3] * e1;
            if (r0 < M)
                *reinterpret_cast<float2*>(Cmat + (size_t)r0 * BN + col) =
                    make_float2(acc[mt][nt][0], acc[mt][nt][1]);
            if (r0 + 8 < M)
                *reinterpret_cast<float2*>(Cmat + (size_t)(r0 + 8) * BN + col) =
                    make_float2(acc[mt][nt][2], acc[mt][nt][3]);
        }
        #pragma unroll
        for (int o = 1; o <= 2; o <<= 1) {
            s_lo += __shfl_xor_sync(0xffffffffu, s_lo, o);
            d_lo += __shfl_xor_sync(0xffffffffu, d_lo, o);
            s_hi += __shfl_xor_sync(0xffffffffu, s_hi, o);
            d_hi += __shfl_xor_sync(0xffffffffu, d_hi, o);
        }
        if ((lane & 3) == 0) {
            atomicAdd(&sred[rl], s_lo);
            atomicAdd(&sred[BM + rl], d_lo);
            atomicAdd(&sred[rl + 8], s_hi);
            atomicAdd(&sred[BM + rl + 8], d_hi);
        }
    }
    __syncthreads();
    for (int t = tid; t < BM; t += 256) {
        int gr = rowBase + t;
        if (gr < M) { sv[gr] = sred[t]; dv[gr] = sred[BM + t]; }
    }
}

// ---------------- aggregation: out[i] = act( softmax-weighted sum + b ) ----------------
// Explicit float4 (F=128) / float2 (F=64) gathers, x4-unrolled broadcast loop.
template <int F, int ACT>
__global__ __launch_bounds__(256) void aggregate_kernel(
        const float* __restrict__ h, const float* __restrict__ sv,
        const float* __restrict__ dv, const int* __restrict__ rowptr,
        const int* __restrict__ colidx, const float* __restrict__ bias,
        float* __restrict__ out, int n) {
    constexpr int V = F / 32;
    int warp = (blockIdx.x * blockDim.x + threadIdx.x) >> 5;
    int lane = threadIdx.x & 31;
    if (warp >= n) return;
    int i = warp;
    int start = rowptr[i], end = rowptr[i + 1];
    float di = dv[i];

    float m = -INFINITY;
    for (int j = start + lane; j < end; j += 32) {
        float x = sv[colidx[j]] + di;
        x = (x > 0.f) ? x : 0.2f * x;
        m = fmaxf(m, x);
    }
    #pragma unroll
    for (int o = 16; o; o >>= 1) m = fmaxf(m, __shfl_xor_sync(0xffffffffu, m, o));

    float a0 = 0.f, a1 = 0.f, a2 = 0.f, a3 = 0.f;
    float Z = 0.f;

    for (int j0 = start; j0 < end; j0 += 32) {
        int j = j0 + lane;
        int sn = 0;
        float w = 0.f;
        if (j < end) {
            sn = colidx[j];
            float x = sv[sn] + di;
            x = (x > 0.f) ? x : 0.2f * x;
            w = __expf(x - m);
            Z += w;
        }
        int cnt = min(32, end - j0);
        int t = 0;
        for (; t + 4 <= cnt; t += 4) {
            int s0 = __shfl_sync(0xffffffffu, sn, t);
            int s1 = __shfl_sync(0xffffffffu, sn, t + 1);
            int s2 = __shfl_sync(0xffffffffu, sn, t + 2);
            int s3 = __shfl_sync(0xffffffffu, sn, t + 3);
            float w0 = __shfl_sync(0xffffffffu, w, t);
            float w1 = __shfl_sync(0xffffffffu, w, t + 1);
            float w2 = __shfl_sync(0xffffffffu, w, t + 2);
            float w3 = __shfl_sync(0xffffffffu, w, t + 3);
            if (V == 4) {
                float4 x0 = *reinterpret_cast<const float4*>(h + (size_t)s0 * F + 4 * lane);
                float4 x1 = *reinterpret_cast<const float4*>(h + (size_t)s1 * F + 4 * lane);
                float4 x2 = *reinterpret_cast<const float4*>(h + (size_t)s2 * F + 4 * lane);
                float4 x3 = *reinterpret_cast<const float4*>(h + (size_t)s3 * F + 4 * lane);
                a0 += w0 * x0.x + w1 * x1.x + w2 * x2.x + w3 * x3.x;
                a1 += w0 * x0.y + w1 * x1.y + w2 * x2.y + w3 * x3.y;
                a2 += w0 * x0.z + w1 * x1.z + w2 * x2.z + w3 * x3.z;
                a3 += w0 * x0.w + w1 * x1.w + w2 * x2.w + w3 * x3.w;
            } else {
                float2 x0 = *reinterpret_cast<const float2*>(h + (size_t)s0 * F + 2 * lane);
                float2 x1 = *reinterpret_cast<const float2*>(h + (size_t)s1 * F + 2 * lane);
                float2 x2 = *reinterpret_cast<const float2*>(h + (size_t)s2 * F + 2 * lane);
                float2 x3 = *reinterpret_cast<const float2*>(h + (size_t)s3 * F + 2 * lane);
                a0 += w0 * x0.x + w1 * x1.x + w2 * x2.x + w3 * x3.x;
                a1 += w0 * x0.y + w1 * x1.y + w2 * x2.y + w3 * x3.y;
            }
        }
        for (; t < cnt; t++) {
            int sb = __shfl_sync(0xffffffffu, sn, t);
            float wb = __shfl_sync(0xffffffffu, w, t);
            if (V == 4) {
                float4 x0 = *reinterpret_cast<const float4*>(h + (size_t)sb * F + 4 * lane);
                a0 += wb * x0.x; a1 += wb * x0.y; a2 += wb * x0.z; a3 += wb * x0.w;
            } else {
                float2 x0 = *reinterpret_cast<const float2*>(h + (size_t)sb * F + 2 * lane);
                a0 += wb * x0.x; a1 += wb * x0.y;
            }
        }
    }
    #pragma unroll
    for (int o = 16; o; o >>= 1) Z += __shfl_xor_sync(0xffffffffu, Z, o);
    float invZ = 1.f / (Z + 1e-16f);

    if (V == 4) {
        float4 bb = *reinterpret_cast<const float4*>(bias + 4 * lane);
        float4 r;
        r.x = a0 * invZ + bb.x; r.y = a1 * invZ + bb.y;
        r.z = a2 * invZ + bb.z; r.w = a3 * invZ + bb.w;
        if (ACT == 0) {
            r.x = fmaxf(r.x, 0.f); r.y = fmaxf(r.y, 0.f);
            r.z = fmaxf(r.z, 0.f); r.w = fmaxf(r.w, 0.f);
        } else {
            r.x = 1.f / (1.f + __expf(-r.x)); r.y = 1.f / (1.f + __expf(-r.y));
            r.z = 1.f / (1.f + __expf(-r.z)); r.w = 1.f / (1.f + __expf(-r.w));
        }
        *reinterpret_cast<float4*>(out + (size_t)i * F + 4 * lane) = r;
    } else {
        float2 bb = *reinterpret_cast<const float2*>(bias + 2 * lane);
        float2 r;
        r.x = a0 * invZ + bb.x; r.y = a1 * invZ + bb.y;
        if (ACT == 0) { r.x = fmaxf(r.x, 0.f); r.y = fmaxf(r.y, 0.f); }
        else { r.x = 1.f / (1.f + __expf(-r.x)); r.y = 1.f / (1.f + __expf(-r.y)); }
        *reinterpret_cast<float2*>(out + (size_t)i * F + 2 * lane) = r;
    }
}

// ---------------- host launch ----------------
static inline int cdiv(int a, int b) { return (a + b - 1) / b; }

extern "C" void kernel_launch(void* const* d_in, const int* in_sizes, int n_in,
                              void* d_out, int out_size) {
    const int*   ei    = (const int*)d_in[0];
    const float* embed = (const float*)d_in[1];
    const float* W1    = (const float*)d_in[2];
    const float* as1   = (const float*)d_in[3];
    const float* ad1   = (const float*)d_in[4];
    const float* b1    = (const float*)d_in[5];
    const float* W2    = (const float*)d_in[6];
    const float* as2   = (const float*)d_in[7];
    const float* ad2   = (const float*)d_in[8];
    const float* b2    = (const float*)d_in[9];

    int E = in_sizes[0] / 2;
    int N = in_sizes[1] / CDIM;
    const int* srcv = ei;
    const int* dstv = ei + E;

    void* p;
    cudaGetSymbolAddress(&p, g_deg);    int* deg    = (int*)p;
    cudaGetSymbolAddress(&p, g_incl);   int* incl   = (int*)p;
    cudaGetSymbolAddress(&p, g_bsums);  int* bsums  = (int*)p;
    cudaGetSymbolAddress(&p, g_rowptr); int* rowptr = (int*)p;
    cudaGetSymbolAddress(&p, g_pos);    int* pos    = (int*)p;
    cudaGetSymbolAddress(&p, g_col);    int* col    = (int*)p;
    cudaGetSymbolAddress(&p, g_h1);     float* h1   = (float*)p;
    cudaGetSymbolAddress(&p, g_x1);     float* x1   = (float*)p;
    cudaGetSymbolAddress(&p, g_h2);     float* h2   = (float*)p;
    cudaGetSymbolAddress(&p, g_s1);     float* s1   = (float*)p;
    cudaGetSymbolAddress(&p, g_d1);     float* d1   = (float*)p;
    cudaGetSymbolAddress(&p, g_s2);     float* s2   = (float*)p;
    cudaGetSymbolAddress(&p, g_d2);     float* d2   = (float*)p;
    float* out = (float*)d_out;

    int nb = cdiv(N, 1024);

    // dynamic smem opt-in (not stream ops; graph-capture safe, idempotent)
    constexpr int SMEM1 = (2 * 128 * 36 + 2 * 32 * (HDIM + 8)) * 4;  // 71680
    constexpr int SMEM2 = (2 * 128 * 36 + 2 * 32 * (KOUT + 8)) * 4;  // 55296
    static bool attrs_set = false;
    if (!attrs_set) {
        cudaFuncSetAttribute(mma_gemm_kernel<HDIM, CDIM>,
                             cudaFuncAttributeMaxDynamicSharedMemorySize, SMEM1);
        cudaFuncSetAttribute(mma_gemm_kernel<KOUT, HDIM>,
                             cudaFuncAttributeMaxDynamicSharedMemorySize, SMEM2);
        attrs_set = true;
    }

    // CSR build interleaved with independent GEMM1
    init_deg_kernel<<<cdiv(N, 256), 256>>>(deg, N);
    hist_kernel<<<cdiv(E, 256), 256>>>(dstv, deg, E);
    scan_block_kernel<<<nb, 1024>>>(deg, incl, bsums, N);
    mma_gemm_kernel<HDIM, CDIM><<<cdiv(N, 128), 256, SMEM1>>>(embed, W1, h1, as1, ad1, s1, d1, N);
    scan_bsums_kernel<<<1, 128>>>(bsums, nb);
    finalize_rowptr_kernel<<<cdiv(N + 1, 256), 256>>>(incl, bsums, deg, rowptr, pos, N);
    scatter_kernel<<<cdiv(E, 256), 256>>>(srcv, dstv, pos, col, E);
    selfloop_kernel<<<cdiv(N, 256), 256>>>(pos, col, N);

    // Layer 1 aggregation
    aggregate_kernel<HDIM, 0><<<cdiv(N, 8), 256>>>(h1, s1, d1, rowptr, col, b1, x1, N);

    // Layer 2
    mma_gemm_kernel<KOUT, HDIM><<<cdiv(N, 128), 256, SMEM2>>>(x1, W2, h2, as2, ad2, s2, d2, N);
    aggregate_kernel<KOUT, 1><<<cdiv(N, 8), 256>>>(h2, s2, d2, rowptr, col, b2, out, N);
}

// round 5
// speedup vs baseline: 1.4388x; 1.0814x over previous
#include <cuda_runtime.h>
#include <cuda_fp16.h>
#include <math.h>
#include <stdint.h>

// Problem-fixed shapes: N=100000, C=256, H=128, K=64, E=1600000
#define NN   100000
#define EE   1600000
#define ETOT (EE + NN)
#define CDIM 256
#define HDIM 128
#define KOUT 64

// ---------------- device scratch (static, no allocation) ----------------
__device__ int    g_deg[NN];
__device__ int    g_incl[NN];
__device__ int    g_bsums[256];
__device__ int    g_rowptr[NN + 1];
__device__ int    g_pos[NN];
__device__ int    g_col[ETOT];
__device__ __half g_h1[NN * HDIM];
__device__ float  g_x1[NN * HDIM];
__device__ __half g_h2[NN * KOUT];
__device__ float  g_s1[NN], g_d1[NN], g_s2[NN], g_d2[NN];

// ---------------- CSR build ----------------
__global__ void init_deg_kernel(int* deg, int n) {
    int i = blockIdx.x * blockDim.x + threadIdx.x;
    if (i < n) deg[i] = 1;  // self-loop
}

__global__ void hist_kernel(const int* __restrict__ dst, int* deg, int e) {
    int i = blockIdx.x * blockDim.x + threadIdx.x;
    if (i < e) atomicAdd(&deg[dst[i]], 1);
}

__global__ void scan_block_kernel(const int* __restrict__ deg, int* incl, int* bsums, int n) {
    __shared__ int sh[1024];
    int t = threadIdx.x;
    int gid = blockIdx.x * 1024 + t;
    sh[t] = (gid < n) ? deg[gid] : 0;
    __syncthreads();
    #pragma unroll
    for (int off = 1; off < 1024; off <<= 1) {
        int v = (t >= off) ? sh[t - off] : 0;
        __syncthreads();
        sh[t] += v;
        __syncthreads();
    }
    if (gid < n) incl[gid] = sh[t];
    if (t == 1023) bsums[blockIdx.x] = sh[t];
}

__global__ void scan_bsums_kernel(int* bsums, int nb) {
    __shared__ int sh[128];
    int t = threadIdx.x;
    sh[t] = (t < nb) ? bsums[t] : 0;
    __syncthreads();
    #pragma unroll
    for (int off = 1; off < 128; off <<= 1) {
        int v = (t >= off) ? sh[t - off] : 0;
        __syncthreads();
        sh[t] += v;
        __syncthreads();
    }
    if (t < nb) bsums[t] = (t == 0) ? 0 : sh[t - 1];
}

__global__ void finalize_rowptr_kernel(const int* __restrict__ incl, const int* __restrict__ bsums,
                                       const int* __restrict__ deg, int* rowptr, int* pos, int n) {
    int gid = blockIdx.x * blockDim.x + threadIdx.x;
    if (gid < n) {
        int v = incl[gid] + bsums[gid >> 10];
        rowptr[gid + 1] = v;
        pos[gid] = v - deg[gid];
    }
    if (gid == 0) rowptr[0] = 0;
}

// edges [0,e) + self-loops [e, e+n)
__global__ void scatter_kernel(const int* __restrict__ srcv, const int* __restrict__ dstv,
                               int* pos, int* colv, int e, int n) {
    int i = blockIdx.x * blockDim.x + threadIdx.x;
    if (i < e) {
        int p = atomicAdd(&pos[dstv[i]], 1);
        colv[p] = srcv[i];
    } else if (i < e + n) {
        int v = i - e;
        int p = atomicAdd(&pos[v], 1);
        colv[p] = v;
    }
}

// ---------------- cp.async helpers ----------------
__device__ __forceinline__ void cp_async16(void* smem_dst, const void* gmem_src, bool pred) {
    uint32_t saddr = (uint32_t)__cvta_generic_to_shared(smem_dst);
    int sz = pred ? 16 : 0;
    asm volatile("cp.async.cg.shared.global [%0], [%1], 16, %2;\n"
                 :: "r"(saddr), "l"(gmem_src), "r"(sz));
}
__device__ __forceinline__ void cp_commit() {
    asm volatile("cp.async.commit_group;\n");
}
template <int N>
__device__ __forceinline__ void cp_wait() {
    asm volatile("cp.async.wait_group %0;\n" :: "n"(N));
}

// ---------------- tf32 tensor-core GEMM, 2-stage cp.async pipeline ----------------
// C(half)[M x BN] = A[M x KD] * B[KD x BN]; fused sv/dv attention dots (fp32).
template <int BN, int KD>
__global__ __launch_bounds__(256) void mma_gemm_kernel(const float* __restrict__ A,
                                                       const float* __restrict__ B,
                                                       __half* __restrict__ Cmat,
                                                       const float* __restrict__ asrc,
                                                       const float* __restrict__ adst,
                                                       float* __restrict__ sv,
                                                       float* __restrict__ dv, int M) {
    constexpr int BM = 128, BK = 32;
    constexpr int WN = BN / 4;
    constexpr int MT = 4;
    constexpr int NT = WN / 8;
    constexpr int AST = BK + 4;
    constexpr int BST = BN + 8;
    constexpr int T = KD / BK;

    extern __shared__ float smem[];
    float* AsBase = smem;                     // [2][BM][AST]
    float* BsBase = smem + 2 * BM * AST;      // [2][BK][BST]

    int tid = threadIdx.x;
    int lane = tid & 31;
    int wid = tid >> 5;
    int wm = wid & 1;
    int wn = wid >> 1;
    int rowBase = blockIdx.x * BM;

    float acc[MT][NT][4];
    #pragma unroll
    for (int i = 0; i < MT; i++)
        #pragma unroll
        for (int j = 0; j < NT; j++)
            #pragma unroll
            for (int r = 0; r < 4; r++) acc[i][j][r] = 0.f;

    auto loadTiles = [&](int stage, int k0) {
        float* As = AsBase + stage * BM * AST;
        float* Bs = BsBase + stage * BK * BST;
        #pragma unroll
        for (int it = 0; it < 4; it++) {
            int idx = tid + 256 * it;
            int row = idx >> 3;
            int q = idx & 7;
            int gr = rowBase + row;
            cp_async16(As + row * AST + 4 * q,
                       A + (size_t)gr * KD + k0 + 4 * q, gr < M);
        }
        constexpr int BQ = BN / 4;
        constexpr int BIT = (BK * BQ) / 256;
        #pragma unroll
        for (int it = 0; it < BIT; it++) {
            int idx = tid + 256 * it;
            int row = idx / BQ;
            int q = idx % BQ;
            cp_async16(Bs + row * BST + 4 * q,
                       B + (size_t)(k0 + row) * BN + 4 * q, true);
        }
        cp_commit();
    };

    loadTiles(0, 0);

    for (int t = 0; t < T; t++) {
        int st = t & 1;
        if (t + 1 < T) {
            loadTiles((t + 1) & 1, (t + 1) * BK);
            cp_wait<1>();
        } else {
            cp_wait<0>();
        }
        __syncthreads();

        const float* As = AsBase + st * BM * AST;
        const float* Bs = BsBase + st * BK * BST;
        #pragma unroll
        for (int kk = 0; kk < BK / 8; kk++) {
            uint32_t af[MT][4];
            #pragma unroll
            for (int mt = 0; mt < MT; mt++) {
                int r0 = wm * 64 + mt * 16 + (lane >> 2);
                int c0 = 8 * kk + (lane & 3);
                af[mt][0] = __float_as_uint(As[r0 * AST + c0]);
                af[mt][1] = __float_as_uint(As[(r0 + 8) * AST + c0]);
                af[mt][2] = __float_as_uint(As[r0 * AST + c0 + 4]);
                af[mt][3] = __float_as_uint(As[(r0 + 8) * AST + c0 + 4]);
            }
            uint32_t bf[NT][2];
            #pragma unroll
            for (int nt = 0; nt < NT; nt++) {
                int col = wn * WN + nt * 8 + (lane >> 2);
                int kr = 8 * kk + (lane & 3);
                bf[nt][0] = __float_as_uint(Bs[kr * BST + col]);
                bf[nt][1] = __float_as_uint(Bs[(kr + 4) * BST + col]);
            }
            #pragma unroll
            for (int mt = 0; mt < MT; mt++)
                #pragma unroll
                for (int nt = 0; nt < NT; nt++) {
                    asm volatile(
                        "mma.sync.aligned.m16n8k8.row.col.f32.tf32.tf32.f32 "
                        "{%0,%1,%2,%3}, {%4,%5,%6,%7}, {%8,%9}, {%0,%1,%2,%3};"
                        : "+f"(acc[mt][nt][0]), "+f"(acc[mt][nt][1]),
                          "+f"(acc[mt][nt][2]), "+f"(acc[mt][nt][3])
                        : "r"(af[mt][0]), "r"(af[mt][1]), "r"(af[mt][2]), "r"(af[mt][3]),
                          "r"(bf[nt][0]), "r"(bf[nt][1]));
                }
        }
        __syncthreads();
    }

    // epilogue: dot-reduction buffer overlays freed smem
    float* sred = smem;  // [2][BM]
    for (int t = tid; t < 2 * BM; t += 256) sred[t] = 0.f;
    __syncthreads();

    #pragma unroll
    for (int mt = 0; mt < MT; mt++) {
        int rl = wm * 64 + mt * 16 + (lane >> 2);
        int r0 = rowBase + rl;
        float s_lo = 0.f, d_lo = 0.f, s_hi = 0.f, d_hi = 0.f;
        #pragma unroll
        for (int nt = 0; nt < NT; nt++) {
            int col = wn * WN + nt * 8 + 2 * (lane & 3);
            float a0 = asrc[col], a1 = asrc[col + 1];
            float e0 = adst[col], e1 = adst[col + 1];
            s_lo += acc[mt][nt][0] * a0 + acc[mt][nt][1] * a1;
            d_lo += acc[mt][nt][0] * e0 + acc[mt][nt][1] * e1;
            s_hi += acc[mt][nt][2] * a0 + acc[mt][nt][3] * a1;
            d_hi += acc[mt][nt][2] * e0 + acc[mt][nt][3] * e1;
            if (r0 < M)
                *reinterpret_cast<__half2*>(Cmat + (size_t)r0 * BN + col) =
                    __floats2half2_rn(acc[mt][nt][0], acc[mt][nt][1]);
            if (r0 + 8 < M)
                *reinterpret_cast<__half2*>(Cmat + (size_t)(r0 + 8) * BN + col) =
                    __floats2half2_rn(acc[mt][nt][2], acc[mt][nt][3]);
        }
        #pragma unroll
        for (int o = 1; o <= 2; o <<= 1) {
            s_lo += __shfl_xor_sync(0xffffffffu, s_lo, o);
            d_lo += __shfl_xor_sync(0xffffffffu, d_lo, o);
            s_hi += __shfl_xor_sync(0xffffffffu, s_hi, o);
            d_hi += __shfl_xor_sync(0xffffffffu, d_hi, o);
        }
        if ((lane & 3) == 0) {
            atomicAdd(&sred[rl], s_lo);
            atomicAdd(&sred[BM + rl], d_lo);
            atomicAdd(&sred[rl + 8], s_hi);
            atomicAdd(&sred[BM + rl + 8], d_hi);
        }
    }
    __syncthreads();
    for (int t = tid; t < BM; t += 256) {
        int gr = rowBase + t;
        if (gr < M) { sv[gr] = sred[t]; dv[gr] = sred[BM + t]; }
    }
}

// ---------------- aggregation (fp16 gather): out = act(softmax-sum + b), fp32 out ----------------
template <int F, int ACT>
__global__ __launch_bounds__(256) void aggregate_kernel(
        const __half* __restrict__ h, const float* __restrict__ sv,
        const float* __restrict__ dv, const int* __restrict__ rowptr,
        const int* __restrict__ colidx, const float* __restrict__ bias,
        float* __restrict__ out, int n) {
    constexpr int V = F / 32;  // halves per lane: 4 (F=128) or 2 (F=64)
    int warp = (blockIdx.x * blockDim.x + threadIdx.x) >> 5;
    int lane = threadIdx.x & 31;
    if (warp >= n) return;
    int i = warp;
    int start = rowptr[i], end = rowptr[i + 1];
    float di = dv[i];

    float m = -INFINITY;
    for (int j = start + lane; j < end; j += 32) {
        float x = sv[colidx[j]] + di;
        x = (x > 0.f) ? x : 0.2f * x;
        m = fmaxf(m, x);
    }
    #pragma unroll
    for (int o = 16; o; o >>= 1) m = fmaxf(m, __shfl_xor_sync(0xffffffffu, m, o));

    float a0 = 0.f, a1 = 0.f, a2 = 0.f, a3 = 0.f;
    float Z = 0.f;

    auto accum = [&](int s, float w) {
        if (V == 4) {
            uint2 u = *reinterpret_cast<const uint2*>(h + (size_t)s * F + 4 * lane);
            float2 f01 = __half22float2(*reinterpret_cast<__half2*>(&u.x));
            float2 f23 = __half22float2(*reinterpret_cast<__half2*>(&u.y));
            a0 += w * f01.x; a1 += w * f01.y; a2 += w * f23.x; a3 += w * f23.y;
        } else {
            __half2 u = *reinterpret_cast<const __half2*>(h + (size_t)s * F + 2 * lane);
            float2 f01 = __half22float2(u);
            a0 += w * f01.x; a1 += w * f01.y;
        }
    };

    for (int j0 = start; j0 < end; j0 += 32) {
        int j = j0 + lane;
        int sn = 0;
        float w = 0.f;
        if (j < end) {
            sn = colidx[j];
            float x = sv[sn] + di;
            x = (x > 0.f) ? x : 0.2f * x;
            w = __expf(x - m);
            Z += w;
        }
        int cnt = min(32, end - j0);
        int t = 0;
        for (; t + 4 <= cnt; t += 4) {
            int s0 = __shfl_sync(0xffffffffu, sn, t);
            int s1 = __shfl_sync(0xffffffffu, sn, t + 1);
            int s2 = __shfl_sync(0xffffffffu, sn, t + 2);
            int s3 = __shfl_sync(0xffffffffu, sn, t + 3);
            float w0 = __shfl_sync(0xffffffffu, w, t);
            float w1 = __shfl_sync(0xffffffffu, w, t + 1);
            float w2 = __shfl_sync(0xffffffffu, w, t + 2);
            float w3 = __shfl_sync(0xffffffffu, w, t + 3);
            accum(s0, w0); accum(s1, w1); accum(s2, w2); accum(s3, w3);
        }
        for (; t < cnt; t++) {
            int sb = __shfl_sync(0xffffffffu, sn, t);
            float wb = __shfl_sync(0xffffffffu, w, t);
            accum(sb, wb);
        }
    }
    #pragma unroll
    for (int o = 16; o; o >>= 1) Z += __shfl_xor_sync(0xffffffffu, Z, o);
    float invZ = 1.f / (Z + 1e-16f);

    if (V == 4) {
        float4 bb = *reinterpret_cast<const float4*>(bias + 4 * lane);
        float4 r;
        r.x = a0 * invZ + bb.x; r.y = a1 * invZ + bb.y;
        r.z = a2 * invZ + bb.z; r.w = a3 * invZ + bb.w;
        if (ACT == 0) {
            r.x = fmaxf(r.x, 0.f); r.y = fmaxf(r.y, 0.f);
            r.z = fmaxf(r.z, 0.f); r.w = fmaxf(r.w, 0.f);
        } else {
            r.x = 1.f / (1.f + __expf(-r.x)); r.y = 1.f / (1.f + __expf(-r.y));
            r.z = 1.f / (1.f + __expf(-r.z)); r.w = 1.f / (1.f + __expf(-r.w));
        }
        *reinterpret_cast<float4*>(out + (size_t)i * F + 4 * lane) = r;
    } else {
        float2 bb = *reinterpret_cast<const float2*>(bias + 2 * lane);
        float2 r;
        r.x = a0 * invZ + bb.x; r.y = a1 * invZ + bb.y;
        if (ACT == 0) { r.x = fmaxf(r.x, 0.f); r.y = fmaxf(r.y, 0.f); }
        else { r.x = 1.f / (1.f + __expf(-r.x)); r.y = 1.f / (1.f + __expf(-r.y)); }
        *reinterpret_cast<float2*>(out + (size_t)i * F + 2 * lane) = r;
    }
}

// ---------------- host launch ----------------
static inline int cdiv(int a, int b) { return (a + b - 1) / b; }

extern "C" void kernel_launch(void* const* d_in, const int* in_sizes, int n_in,
                              void* d_out, int out_size) {
    const int*   ei    = (const int*)d_in[0];
    const float* embed = (const float*)d_in[1];
    const float* W1    = (const float*)d_in[2];
    const float* as1   = (const float*)d_in[3];
    const float* ad1   = (const float*)d_in[4];
    const float* b1    = (const float*)d_in[5];
    const float* W2    = (const float*)d_in[6];
    const float* as2   = (const float*)d_in[7];
    const float* ad2   = (const float*)d_in[8];
    const float* b2    = (const float*)d_in[9];

    int E = in_sizes[0] / 2;
    int N = in_sizes[1] / CDIM;
    const int* srcv = ei;
    const int* dstv = ei + E;

    void* p;
    cudaGetSymbolAddress(&p, g_deg);    int* deg    = (int*)p;
    cudaGetSymbolAddress(&p, g_incl);   int* incl   = (int*)p;
    cudaGetSymbolAddress(&p, g_bsums);  int* bsums  = (int*)p;
    cudaGetSymbolAddress(&p, g_rowptr); int* rowptr = (int*)p;
    cudaGetSymbolAddress(&p, g_pos);    int* pos    = (int*)p;
    cudaGetSymbolAddress(&p, g_col);    int* col    = (int*)p;
    cudaGetSymbolAddress(&p, g_h1);     __half* h1  = (__half*)p;
    cudaGetSymbolAddress(&p, g_x1);     float* x1   = (float*)p;
    cudaGetSymbolAddress(&p, g_h2);     __half* h2  = (__half*)p;
    cudaGetSymbolAddress(&p, g_s1);     float* s1   = (float*)p;
    cudaGetSymbolAddress(&p, g_d1);     float* d1   = (float*)p;
    cudaGetSymbolAddress(&p, g_s2);     float* s2   = (float*)p;
    cudaGetSymbolAddress(&p, g_d2);     float* d2   = (float*)p;
    float* out = (float*)d_out;

    int nb = cdiv(N, 1024);

    constexpr int SMEM1 = (2 * 128 * 36 + 2 * 32 * (HDIM + 8)) * 4;  // 71680
    constexpr int SMEM2 = (2 * 128 * 36 + 2 * 32 * (KOUT + 8)) * 4;  // 55296
    static bool attrs_set = false;
    if (!attrs_set) {
        cudaFuncSetAttribute(mma_gemm_kernel<HDIM, CDIM>,
                             cudaFuncAttributeMaxDynamicSharedMemorySize, SMEM1);
        cudaFuncSetAttribute(mma_gemm_kernel<KOUT, HDIM>,
                             cudaFuncAttributeMaxDynamicSharedMemorySize, SMEM2);
        attrs_set = true;
    }

    // CSR build interleaved with independent GEMM1 (GEMM1 at launch index 3 for ncu)
    init_deg_kernel<<<cdiv(N, 256), 256>>>(deg, N);
    hist_kernel<<<cdiv(E, 256), 256>>>(dstv, deg, E);
    scan_block_kernel<<<nb, 1024>>>(deg, incl, bsums, N);
    mma_gemm_kernel<HDIM, CDIM><<<cdiv(N, 128), 256, SMEM1>>>(embed, W1, h1, as1, ad1, s1, d1, N);
    scan_bsums_kernel<<<1, 128>>>(bsums, nb);
    finalize_rowptr_kernel<<<cdiv(N + 1, 256), 256>>>(incl, bsums, deg, rowptr, pos, N);
    scatter_kernel<<<cdiv(E + N, 256), 256>>>(srcv, dstv, pos, col, E, N);

    // Layer 1 aggregation (fp16 gather -> fp32 x1)
    aggregate_kernel<HDIM, 0><<<cdiv(N, 8), 256>>>(h1, s1, d1, rowptr, col, b1, x1, N);

    // Layer 2
    mma_gemm_kernel<KOUT, HDIM><<<cdiv(N, 128), 256, SMEM2>>>(x1, W2, h2, as2, ad2, s2, d2, N);
    aggregate_kernel<KOUT, 1><<<cdiv(N, 8), 256>>>(h2, s2, d2, rowptr, col, b2, out, N);
}

// round 6
// speedup vs baseline: 1.5260x; 1.0606x over previous
#include <cuda_runtime.h>
#include <cuda_fp16.h>
#include <math.h>
#include <stdint.h>

// Problem-fixed shapes: N=100000, C=256, H=128, K=64, E=1600000
#define NN   100000
#define EE   1600000
#define ETOT (EE + NN)
#define CDIM 256
#define HDIM 128
#define KOUT 64

// ---------------- device scratch (static, no allocation) ----------------
__device__ int    g_deg[NN];
__device__ int    g_incl[NN];
__device__ int    g_bsums[256];
__device__ int    g_rowptr[NN + 1];
__device__ int    g_pos[NN];
__device__ int    g_col[ETOT];
__device__ __half g_h1[NN * HDIM];
__device__ __half g_x1[NN * HDIM];
__device__ __half g_h2[NN * KOUT];
__device__ __half g_w1t[HDIM * CDIM];
__device__ __half g_w2t[KOUT * HDIM];
__device__ float  g_s1[NN], g_d1[NN], g_s2[NN], g_d2[NN];

// ---------------- weight transpose + fp16 convert: WT[n][k] = W[k][n] ----------------
template <int KD, int BN>
__global__ void wtrans_kernel(const float* __restrict__ W, __half* __restrict__ WT) {
    int idx = blockIdx.x * blockDim.x + threadIdx.x;
    if (idx < KD * BN) {
        int n = idx / KD, k = idx % KD;
        WT[idx] = __float2half(W[(size_t)k * BN + n]);
    }
}

// ---------------- CSR build ----------------
__global__ void init_deg_kernel(int* deg, int n) {
    int i = blockIdx.x * blockDim.x + threadIdx.x;
    if (i < n) deg[i] = 1;  // self-loop
}

__global__ void hist_kernel(const int* __restrict__ dst, int* deg, int e) {
    int i = blockIdx.x * blockDim.x + threadIdx.x;
    if (i < e) atomicAdd(&deg[dst[i]], 1);
}

__global__ void scan_block_kernel(const int* __restrict__ deg, int* incl, int* bsums, int n) {
    __shared__ int sh[1024];
    int t = threadIdx.x;
    int gid = blockIdx.x * 1024 + t;
    sh[t] = (gid < n) ? deg[gid] : 0;
    __syncthreads();
    #pragma unroll
    for (int off = 1; off < 1024; off <<= 1) {
        int v = (t >= off) ? sh[t - off] : 0;
        __syncthreads();
        sh[t] += v;
        __syncthreads();
    }
    if (gid < n) incl[gid] = sh[t];
    if (t == 1023) bsums[blockIdx.x] = sh[t];
}

__global__ void scan_bsums_kernel(int* bsums, int nb) {
    __shared__ int sh[128];
    int t = threadIdx.x;
    sh[t] = (t < nb) ? bsums[t] : 0;
    __syncthreads();
    #pragma unroll
    for (int off = 1; off < 128; off <<= 1) {
        int v = (t >= off) ? sh[t - off] : 0;
        __syncthreads();
        sh[t] += v;
        __syncthreads();
    }
    if (t < nb) bsums[t] = (t == 0) ? 0 : sh[t - 1];
}

__global__ void finalize_rowptr_kernel(const int* __restrict__ incl, const int* __restrict__ bsums,
                                       const int* __restrict__ deg, int* rowptr, int* pos, int n) {
    int gid = blockIdx.x * blockDim.x + threadIdx.x;
    if (gid < n) {
        int v = incl[gid] + bsums[gid >> 10];
        rowptr[gid + 1] = v;
        pos[gid] = v - deg[gid];
    }
    if (gid == 0) rowptr[0] = 0;
}

__global__ void scatter_kernel(const int* __restrict__ srcv, const int* __restrict__ dstv,
                               int* pos, int* colv, int e, int n) {
    int i = blockIdx.x * blockDim.x + threadIdx.x;
    if (i < e) {
        int p = atomicAdd(&pos[dstv[i]], 1);
        colv[p] = srcv[i];
    } else if (i < e + n) {
        int v = i - e;
        int p = atomicAdd(&pos[v], 1);
        colv[p] = v;
    }
}

// ---------------- cp.async helpers ----------------
__device__ __forceinline__ void cp_async16(void* smem_dst, const void* gmem_src, bool pred) {
    uint32_t saddr = (uint32_t)__cvta_generic_to_shared(smem_dst);
    int sz = pred ? 16 : 0;
    asm volatile("cp.async.cg.shared.global [%0], [%1], 16, %2;\n"
                 :: "r"(saddr), "l"(gmem_src), "r"(sz));
}
__device__ __forceinline__ void cp_commit() {
    asm volatile("cp.async.commit_group;\n");
}
template <int N>
__device__ __forceinline__ void cp_wait() {
    asm volatile("cp.async.wait_group %0;\n" :: "n"(N));
}

__device__ __forceinline__ uint32_t h2u(__half2 h) { return *reinterpret_cast<uint32_t*>(&h); }

// ---------------- fp16 tensor-core GEMM (m16n8k16), 2-stage pipeline ----------------
// C(half)[M x BN] = A[M x KD] * BT^T  (BT is [BN][KD] fp16, k-contiguous)
// CONVA: A is fp32 (convert in load path via register prefetch); else A fp16 via cp.async.
// Fused epilogue: sv[i] = C[i,:].asrc, dv[i] = C[i,:].adst  (fp32).
template <int BN, int KD, bool CONVA>
__global__ __launch_bounds__(256) void mma_gemm_kernel(const void* __restrict__ Ap,
                                                       const __half* __restrict__ BT,
                                                       __half* __restrict__ Cmat,
                                                       const float* __restrict__ asrc,
                                                       const float* __restrict__ adst,
                                                       float* __restrict__ sv,
                                                       float* __restrict__ dv, int M) {
    constexpr int BM = 128, BK = 32;
    constexpr int WN = BN / 4;
    constexpr int MT = 4;
    constexpr int NT = WN / 8;
    constexpr int ST = 40;     // smem row stride (halves): (20r + c) % 32 conflict-free
    constexpr int T = KD / BK;

    __shared__ alignas(16) __half As[2][BM][ST];
    __shared__ alignas(16) __half Bs[2][BN][ST];

    int tid = threadIdx.x;
    int lane = tid & 31;
    int wid = tid >> 5;
    int wm = wid & 1;
    int wn = wid >> 1;
    int rowBase = blockIdx.x * BM;

    const float*  Af = (const float*)Ap;
    const __half* Ah = (const __half*)Ap;

    float acc[MT][NT][4];
    #pragma unroll
    for (int i = 0; i < MT; i++)
        #pragma unroll
        for (int j = 0; j < NT; j++)
            #pragma unroll
            for (int r = 0; r < 4; r++) acc[i][j][r] = 0.f;

    // --- B staging: cp.async of fp16 BT tile [BN][BK] ---
    auto loadB = [&](int stage, int k0) {
        constexpr int CH = BN * 4;            // 16B chunks in tile
        constexpr int BIT = CH / 256;         // per-thread chunks (2 or 1)
        #pragma unroll
        for (int it = 0; it < BIT; it++) {
            int idx = tid + 256 * it;
            int n = idx >> 2;
            int qc = idx & 3;
            cp_async16(&Bs[stage][n][8 * qc],
                       BT + (size_t)n * KD + k0 + 8 * qc, true);
        }
        cp_commit();
    };

    // --- A staging ---
    float4 pa[2][2];                           // CONVA register prefetch
    auto ldgA = [&](int k0) {
        #pragma unroll
        for (int it = 0; it < 2; it++) {
            int idx = tid + 256 * it;
            int row = idx >> 2;
            int q = idx & 3;
            int gr = rowBase + row;
            if (gr < M) {
                const float* src = Af + (size_t)gr * KD + k0 + 8 * q;
                pa[it][0] = *reinterpret_cast<const float4*>(src);
                pa[it][1] = *reinterpret_cast<const float4*>(src + 4);
            } else {
                pa[it][0] = make_float4(0.f, 0.f, 0.f, 0.f);
                pa[it][1] = make_float4(0.f, 0.f, 0.f, 0.f);
            }
        }
    };
    auto stsA = [&](int stage) {
        #pragma unroll
        for (int it = 0; it < 2; it++) {
            int idx = tid + 256 * it;
            int row = idx >> 2;
            int q = idx & 3;
            uint4 u;
            u.x = h2u(__floats2half2_rn(pa[it][0].x, pa[it][0].y));
            u.y = h2u(__floats2half2_rn(pa[it][0].z, pa[it][0].w));
            u.z = h2u(__floats2half2_rn(pa[it][1].x, pa[it][1].y));
            u.w = h2u(__floats2half2_rn(pa[it][1].z, pa[it][1].w));
            *reinterpret_cast<uint4*>(&As[stage][row][8 * q]) = u;
        }
    };
    auto cpA = [&](int stage, int k0) {        // fp16 A via cp.async
        #pragma unroll
        for (int it = 0; it < 2; it++) {
            int idx = tid + 256 * it;
            int row = idx >> 2;
            int q = idx & 3;
            int gr = rowBase + row;
            cp_async16(&As[stage][row][8 * q],
                       Ah + (size_t)gr * KD + k0 + 8 * q, gr < M);
        }
    };

    // prologue
    if (CONVA) {
        ldgA(0);
        loadB(0, 0);
    } else {
        cpA(0, 0);
        loadB(0, 0);
    }

    for (int t = 0; t < T; t++) {
        int st = t & 1;
        if (CONVA) {
            stsA(st);                           // regs(tile t) -> smem
            if (t + 1 < T) {
                ldgA((t + 1) * BK);             // prefetch next A into regs
                loadB(st ^ 1, (t + 1) * BK);
                cp_wait<1>();
            } else {
                cp_wait<0>();
            }
        } else {
            if (t + 1 < T) {
                cpA(st ^ 1, (t + 1) * BK);
                loadB(st ^ 1, (t + 1) * BK);
                cp_wait<1>();
            } else {
                cp_wait<0>();
            }
        }
        __syncthreads();

        #pragma unroll
        for (int kk = 0; kk < 2; kk++) {        // two k16 steps
            int kb = 16 * kk + 2 * (lane & 3);
            uint32_t af[MT][4];
            #pragma unroll
            for (int mt = 0; mt < MT; mt++) {
                int r0 = wm * 64 + mt * 16 + (lane >> 2);
                af[mt][0] = *reinterpret_cast<const uint32_t*>(&As[st][r0][kb]);
                af[mt][1] = *reinterpret_cast<const uint32_t*>(&As[st][r0 + 8][kb]);
                af[mt][2] = *reinterpret_cast<const uint32_t*>(&As[st][r0][kb + 8]);
                af[mt][3] = *reinterpret_cast<const uint32_t*>(&As[st][r0 + 8][kb + 8]);
            }
            uint32_t bf[NT][2];
            #pragma unroll
            for (int nt = 0; nt < NT; nt++) {
                int n = wn * WN + nt * 8 + (lane >> 2);
                bf[nt][0] = *reinterpret_cast<const uint32_t*>(&Bs[st][n][kb]);
                bf[nt][1] = *reinterpret_cast<const uint32_t*>(&Bs[st][n][kb + 8]);
            }
            #pragma unroll
            for (int mt = 0; mt < MT; mt++)
                #pragma unroll
                for (int nt = 0; nt < NT; nt++) {
                    asm volatile(
                        "mma.sync.aligned.m16n8k16.row.col.f32.f16.f16.f32 "
                        "{%0,%1,%2,%3}, {%4,%5,%6,%7}, {%8,%9}, {%0,%1,%2,%3};"
                        : "+f"(acc[mt][nt][0]), "+f"(acc[mt][nt][1]),
                          "+f"(acc[mt][nt][2]), "+f"(acc[mt][nt][3])
                        : "r"(af[mt][0]), "r"(af[mt][1]), "r"(af[mt][2]), "r"(af[mt][3]),
                          "r"(bf[nt][0]), "r"(bf[nt][1]));
                }
        }
        __syncthreads();
    }

    // epilogue: dot-reduction buffer overlays smem
    float* sred = reinterpret_cast<float*>(&As[0][0][0]);  // [2][BM]
    for (int t = tid; t < 2 * BM; t += 256) sred[t] = 0.f;
    __syncthreads();

    #pragma unroll
    for (int mt = 0; mt < MT; mt++) {
        int rl = wm * 64 + mt * 16 + (lane >> 2);
        int r0 = rowBase + rl;
        float s_lo = 0.f, d_lo = 0.f, s_hi = 0.f, d_hi = 0.f;
        #pragma unroll
        for (int nt = 0; nt < NT; nt++) {
            int col = wn * WN + nt * 8 + 2 * (lane & 3);
            float a0 = asrc[col], a1 = asrc[col + 1];
            float e0 = adst[col], e1 = adst[col + 1];
            s_lo += acc[mt][nt][0] * a0 + acc[mt][nt][1] * a1;
            d_lo += acc[mt][nt][0] * e0 + acc[mt][nt][1] * e1;
            s_hi += acc[mt][nt][2] * a0 + acc[mt][nt][3] * a1;
            d_hi += acc[mt][nt][2] * e0 + acc[mt][nt][3] * e1;
            if (r0 < M)
                *reinterpret_cast<__half2*>(Cmat + (size_t)r0 * BN + col) =
                    __floats2half2_rn(acc[mt][nt][0], acc[mt][nt][1]);
            if (r0 + 8 < M)
                *reinterpret_cast<__half2*>(Cmat + (size_t)(r0 + 8) * BN + col) =
                    __floats2half2_rn(acc[mt][nt][2], acc[mt][nt][3]);
        }
        #pragma unroll
        for (int o = 1; o <= 2; o <<= 1) {
            s_lo += __shfl_xor_sync(0xffffffffu, s_lo, o);
            d_lo += __shfl_xor_sync(0xffffffffu, d_lo, o);
            s_hi += __shfl_xor_sync(0xffffffffu, s_hi, o);
            d_hi += __shfl_xor_sync(0xffffffffu, d_hi, o);
        }
        if ((lane & 3) == 0) {
            atomicAdd(&sred[rl], s_lo);
            atomicAdd(&sred[BM + rl], d_lo);
            atomicAdd(&sred[rl + 8], s_hi);
            atomicAdd(&sred[BM + rl + 8], d_hi);
        }
    }
    __syncthreads();
    for (int t = tid; t < BM; t += 256) {
        int gr = rowBase + t;
        if (gr < M) { sv[gr] = sred[t]; dv[gr] = sred[BM + t]; }
    }
}

// ---------------- aggregation (fp16 gather): out = act(softmax-sum + b) ----------------
// OUTH: write fp16 (layer 1 -> x1), else fp32 (final output)
template <int F, int ACT, bool OUTH>
__global__ __launch_bounds__(256) void aggregate_kernel(
        const __half* __restrict__ h, const float* __restrict__ sv,
        const float* __restrict__ dv, const int* __restrict__ rowptr,
        const int* __restrict__ colidx, const float* __restrict__ bias,
        void* __restrict__ outp, int n) {
    constexpr int V = F / 32;
    int warp = (blockIdx.x * blockDim.x + threadIdx.x) >> 5;
    int lane = threadIdx.x & 31;
    if (warp >= n) return;
    int i = warp;
    int start = rowptr[i], end = rowptr[i + 1];
    float di = dv[i];

    float m = -INFINITY;
    for (int j = start + lane; j < end; j += 32) {
        float x = sv[colidx[j]] + di;
        x = (x > 0.f) ? x : 0.2f * x;
        m = fmaxf(m, x);
    }
    #pragma unroll
    for (int o = 16; o; o >>= 1) m = fmaxf(m, __shfl_xor_sync(0xffffffffu, m, o));

    float a0 = 0.f, a1 = 0.f, a2 = 0.f, a3 = 0.f;
    float Z = 0.f;

    auto accum = [&](int s, float w) {
        if (V == 4) {
            uint2 u = *reinterpret_cast<const uint2*>(h + (size_t)s * F + 4 * lane);
            float2 f01 = __half22float2(*reinterpret_cast<__half2*>(&u.x));
            float2 f23 = __half22float2(*reinterpret_cast<__half2*>(&u.y));
            a0 += w * f01.x; a1 += w * f01.y; a2 += w * f23.x; a3 += w * f23.y;
        } else {
            __half2 u = *reinterpret_cast<const __half2*>(h + (size_t)s * F + 2 * lane);
            float2 f01 = __half22float2(u);
            a0 += w * f01.x; a1 += w * f01.y;
        }
    };

    for (int j0 = start; j0 < end; j0 += 32) {
        int j = j0 + lane;
        int sn = 0;
        float w = 0.f;
        if (j < end) {
            sn = colidx[j];
            float x = sv[sn] + di;
            x = (x > 0.f) ? x : 0.2f * x;
            w = __expf(x - m);
            Z += w;
        }
        int cnt = min(32, end - j0);
        int t = 0;
        for (; t + 4 <= cnt; t += 4) {
            int s0 = __shfl_sync(0xffffffffu, sn, t);
            int s1 = __shfl_sync(0xffffffffu, sn, t + 1);
            int s2 = __shfl_sync(0xffffffffu, sn, t + 2);
            int s3 = __shfl_sync(0xffffffffu, sn, t + 3);
            float w0 = __shfl_sync(0xffffffffu, w, t);
            float w1 = __shfl_sync(0xffffffffu, w, t + 1);
            float w2 = __shfl_sync(0xffffffffu, w, t + 2);
            float w3 = __shfl_sync(0xffffffffu, w, t + 3);
            accum(s0, w0); accum(s1, w1); accum(s2, w2); accum(s3, w3);
        }
        for (; t < cnt; t++) {
            int sb = __shfl_sync(0xffffffffu, sn, t);
            float wb = __shfl_sync(0xffffffffu, w, t);
            accum(sb, wb);
        }
    }
    #pragma unroll
    for (int o = 16; o; o >>= 1) Z += __shfl_xor_sync(0xffffffffu, Z, o);
    float invZ = 1.f / (Z + 1e-16f);

    float r0, r1, r2 = 0.f, r3 = 0.f;
    if (V == 4) {
        float4 bb = *reinterpret_cast<const float4*>(bias + 4 * lane);
        r0 = a0 * invZ + bb.x; r1 = a1 * invZ + bb.y;
        r2 = a2 * invZ + bb.z; r3 = a3 * invZ + bb.w;
    } else {
        float2 bb = *reinterpret_cast<const float2*>(bias + 2 * lane);
        r0 = a0 * invZ + bb.x; r1 = a1 * invZ + bb.y;
    }
    if (ACT == 0) {
        r0 = fmaxf(r0, 0.f); r1 = fmaxf(r1, 0.f);
        r2 = fmaxf(r2, 0.f); r3 = fmaxf(r3, 0.f);
    } else {
        r0 = 1.f / (1.f + __expf(-r0)); r1 = 1.f / (1.f + __expf(-r1));
        r2 = 1.f / (1.f + __expf(-r2)); r3 = 1.f / (1.f + __expf(-r3));
    }

    if (OUTH) {
        __half* out = (__half*)outp;
        if (V == 4) {
            uint2 u;
            u.x = h2u(__floats2half2_rn(r0, r1));
            u.y = h2u(__floats2half2_rn(r2, r3));
            *reinterpret_cast<uint2*>(out + (size_t)i * F + 4 * lane) = u;
        } else {
            *reinterpret_cast<__half2*>(out + (size_t)i * F + 2 * lane) =
                __floats2half2_rn(r0, r1);
        }
    } else {
        float* out = (float*)outp;
        if (V == 4)
            *reinterpret_cast<float4*>(out + (size_t)i * F + 4 * lane) =
                make_float4(r0, r1, r2, r3);
        else
            *reinterpret_cast<float2*>(out + (size_t)i * F + 2 * lane) =
                make_float2(r0, r1);
    }
}

// ---------------- host launch ----------------
static inline int cdiv(int a, int b) { return (a + b - 1) / b; }

extern "C" void kernel_launch(void* const* d_in, const int* in_sizes, int n_in,
                              void* d_out, int out_size) {
    const int*   ei    = (const int*)d_in[0];
    const float* embed = (const float*)d_in[1];
    const float* W1    = (const float*)d_in[2];
    const float* as1   = (const float*)d_in[3];
    const float* ad1   = (const float*)d_in[4];
    const float* b1    = (const float*)d_in[5];
    const float* W2    = (const float*)d_in[6];
    const float* as2   = (const float*)d_in[7];
    const float* ad2   = (const float*)d_in[8];
    const float* b2    = (const float*)d_in[9];

    int E = in_sizes[0] / 2;
    int N = in_sizes[1] / CDIM;
    const int* srcv = ei;
    const int* dstv = ei + E;

    void* p;
    cudaGetSymbolAddress(&p, g_deg);    int* deg    = (int*)p;
    cudaGetSymbolAddress(&p, g_incl);   int* incl   = (int*)p;
    cudaGetSymbolAddress(&p, g_bsums);  int* bsums  = (int*)p;
    cudaGetSymbolAddress(&p, g_rowptr); int* rowptr = (int*)p;
    cudaGetSymbolAddress(&p, g_pos);    int* pos    = (int*)p;
    cudaGetSymbolAddress(&p, g_col);    int* col    = (int*)p;
    cudaGetSymbolAddress(&p, g_h1);     __half* h1  = (__half*)p;
    cudaGetSymbolAddress(&p, g_x1);     __half* x1  = (__half*)p;
    cudaGetSymbolAddress(&p, g_h2);     __half* h2  = (__half*)p;
    cudaGetSymbolAddress(&p, g_w1t);    __half* w1t = (__half*)p;
    cudaGetSymbolAddress(&p, g_w2t);    __half* w2t = (__half*)p;
    cudaGetSymbolAddress(&p, g_s1);     float* s1   = (float*)p;
    cudaGetSymbolAddress(&p, g_d1);     float* d1   = (float*)p;
    cudaGetSymbolAddress(&p, g_s2);     float* s2   = (float*)p;
    cudaGetSymbolAddress(&p, g_d2);     float* d2   = (float*)p;
    float* out = (float*)d_out;

    int nb = cdiv(N, 1024);

    // launch 0-2: W1 transpose + CSR start; GEMM1 stays at launch index 3 (ncu window)
    wtrans_kernel<CDIM, HDIM><<<cdiv(CDIM * HDIM, 256), 256>>>(W1, w1t);
    init_deg_kernel<<<cdiv(N, 256), 256>>>(deg, N);
    hist_kernel<<<cdiv(E, 256), 256>>>(dstv, deg, E);
    mma_gemm_kernel<HDIM, CDIM, true><<<cdiv(N, 128), 256>>>(embed, w1t, h1, as1, ad1, s1, d1, N);
    wtrans_kernel<HDIM, KOUT><<<cdiv(HDIM * KOUT, 256), 256>>>(W2, w2t);
    scan_block_kernel<<<nb, 1024>>>(deg, incl, bsums, N);
    scan_bsums_kernel<<<1, 128>>>(bsums, nb);
    finalize_rowptr_kernel<<<cdiv(N + 1, 256), 256>>>(incl, bsums, deg, rowptr, pos, N);
    scatter_kernel<<<cdiv(E + N, 256), 256>>>(srcv, dstv, pos, col, E, N);

    // Layer 1 aggregation (fp16 gather -> fp16 x1)
    aggregate_kernel<HDIM, 0, true><<<cdiv(N, 8), 256>>>(h1, s1, d1, rowptr, col, b1, x1, N);

    // Layer 2
    mma_gemm_kernel<KOUT, HDIM, false><<<cdiv(N, 128), 256>>>(x1, w2t, h2, as2, ad2, s2, d2, N);
    aggregate_kernel<KOUT, 1, false><<<cdiv(N, 8), 256>>>(h2, s2, d2, rowptr, col, b2, out, N);
}

// round 7
// speedup vs baseline: 1.6542x; 1.0840x over previous
#include <cuda_runtime.h>
#include <cuda_fp16.h>
#include <math.h>
#include <stdint.h>

// Problem-fixed shapes: N=100000, C=256, H=128, K=64, E=1600000
#define NN   100000
#define EE   1600000
#define ETOT (EE + NN)
#define CDIM 256
#define HDIM 128
#define KOUT 64

// ---------------- device scratch (static, no allocation) ----------------
__device__ int    g_deg[NN];
__device__ int    g_incl[NN];
__device__ int    g_bsums[256];
__device__ int    g_rowptr[NN + 1];
__device__ int    g_pos[NN];
__device__ int    g_col[ETOT];
__device__ __half g_h1[NN * HDIM];
__device__ __half g_x1[NN * HDIM];
__device__ __half g_h2[NN * KOUT];
__device__ __half g_w1t[HDIM * CDIM];
__device__ __half g_w2t[KOUT * HDIM];
__device__ float  g_s1[NN], g_d1[NN], g_s2[NN], g_d2[NN];

// ---------------- weight transpose + fp16 convert: WT[n][k] = W[k][n] ----------------
template <int KD, int BN>
__global__ void wtrans_kernel(const float* __restrict__ W, __half* __restrict__ WT) {
    int idx = blockIdx.x * blockDim.x + threadIdx.x;
    if (idx < KD * BN) {
        int n = idx / KD, k = idx % KD;
        WT[idx] = __float2half(W[(size_t)k * BN + n]);
    }
}

// ---------------- CSR build ----------------
__global__ void init_deg_kernel(int* deg, int n) {
    int i = blockIdx.x * blockDim.x + threadIdx.x;
    if (i < n) deg[i] = 1;  // self-loop
}

__global__ void hist_kernel(const int* __restrict__ dst, int* deg, int e) {
    int i = blockIdx.x * blockDim.x + threadIdx.x;
    if (i < e) atomicAdd(&deg[dst[i]], 1);
}

__global__ void scan_block_kernel(const int* __restrict__ deg, int* incl, int* bsums, int n) {
    __shared__ int sh[1024];
    int t = threadIdx.x;
    int gid = blockIdx.x * 1024 + t;
    sh[t] = (gid < n) ? deg[gid] : 0;
    __syncthreads();
    #pragma unroll
    for (int off = 1; off < 1024; off <<= 1) {
        int v = (t >= off) ? sh[t - off] : 0;
        __syncthreads();
        sh[t] += v;
        __syncthreads();
    }
    if (gid < n) incl[gid] = sh[t];
    if (t == 1023) bsums[blockIdx.x] = sh[t];
}

__global__ void scan_bsums_kernel(int* bsums, int nb) {
    __shared__ int sh[128];
    int t = threadIdx.x;
    sh[t] = (t < nb) ? bsums[t] : 0;
    __syncthreads();
    #pragma unroll
    for (int off = 1; off < 128; off <<= 1) {
        int v = (t >= off) ? sh[t - off] : 0;
        __syncthreads();
        sh[t] += v;
        __syncthreads();
    }
    if (t < nb) bsums[t] = (t == 0) ? 0 : sh[t - 1];
}

__global__ void finalize_rowptr_kernel(const int* __restrict__ incl, const int* __restrict__ bsums,
                                       const int* __restrict__ deg, int* rowptr, int* pos, int n) {
    int gid = blockIdx.x * blockDim.x + threadIdx.x;
    if (gid < n) {
        int v = incl[gid] + bsums[gid >> 10];
        rowptr[gid + 1] = v;
        pos[gid] = v - deg[gid];
    }
    if (gid == 0) rowptr[0] = 0;
}

__global__ void scatter_kernel(const int* __restrict__ srcv, const int* __restrict__ dstv,
                               int* pos, int* colv, int e, int n) {
    int i = blockIdx.x * blockDim.x + threadIdx.x;
    if (i < e) {
        int p = atomicAdd(&pos[dstv[i]], 1);
        colv[p] = srcv[i];
    } else if (i < e + n) {
        int v = i - e;
        int p = atomicAdd(&pos[v], 1);
        colv[p] = v;
    }
}

// ---------------- asm helpers ----------------
__device__ __forceinline__ void cp_async16(void* smem_dst, const void* gmem_src, bool pred) {
    uint32_t saddr = (uint32_t)__cvta_generic_to_shared(smem_dst);
    int sz = pred ? 16 : 0;
    asm volatile("cp.async.cg.shared.global [%0], [%1], 16, %2;\n"
                 :: "r"(saddr), "l"(gmem_src), "r"(sz));
}
__device__ __forceinline__ void cp_commit() {
    asm volatile("cp.async.commit_group;\n");
}
template <int N>
__device__ __forceinline__ void cp_wait() {
    asm volatile("cp.async.wait_group %0;\n" :: "n"(N));
}
__device__ __forceinline__ uint32_t h2u(__half2 h) { return *reinterpret_cast<uint32_t*>(&h); }
__device__ __forceinline__ void ldsm_x4(uint32_t& r0, uint32_t& r1, uint32_t& r2, uint32_t& r3,
                                        uint32_t addr) {
    asm volatile("ldmatrix.sync.aligned.m8n8.x4.shared.b16 {%0,%1,%2,%3}, [%4];"
                 : "=r"(r0), "=r"(r1), "=r"(r2), "=r"(r3) : "r"(addr));
}

// ---------------- fp16 tensor-core GEMM (m16n8k16), 2-stage pipeline, ldmatrix ----------------
template <int BN, int KD, bool CONVA>
__global__ __launch_bounds__(256) void mma_gemm_kernel(const void* __restrict__ Ap,
                                                       const __half* __restrict__ BT,
                                                       __half* __restrict__ Cmat,
                                                       const float* __restrict__ asrc,
                                                       const float* __restrict__ adst,
                                                       float* __restrict__ sv,
                                                       float* __restrict__ dv, int M) {
    constexpr int BM = 128, BK = 32;
    constexpr int WN = BN / 4;
    constexpr int MT = 4;
    constexpr int NT = WN / 8;
    constexpr int ST = 40;     // smem row stride (halves): LDSM rows hit all 32 banks
    constexpr int T = KD / BK;

    __shared__ alignas(16) __half As[2][BM][ST];
    __shared__ alignas(16) __half Bs[2][BN][ST];

    int tid = threadIdx.x;
    int lane = tid & 31;
    int wid = tid >> 5;
    int wm = wid & 1;
    int wn = wid >> 1;
    int rowBase = blockIdx.x * BM;

    const float*  Af = (const float*)Ap;
    const __half* Ah = (const __half*)Ap;

    float acc[MT][NT][4];
    #pragma unroll
    for (int i = 0; i < MT; i++)
        #pragma unroll
        for (int j = 0; j < NT; j++)
            #pragma unroll
            for (int r = 0; r < 4; r++) acc[i][j][r] = 0.f;

    auto loadB = [&](int stage, int k0) {
        constexpr int CH = BN * 4;
        constexpr int BIT = CH / 256;
        #pragma unroll
        for (int it = 0; it < BIT; it++) {
            int idx = tid + 256 * it;
            int n = idx >> 2;
            int qc = idx & 3;
            cp_async16(&Bs[stage][n][8 * qc],
                       BT + (size_t)n * KD + k0 + 8 * qc, true);
        }
        cp_commit();
    };

    float4 pa[2][2];
    auto ldgA = [&](int k0) {
        #pragma unroll
        for (int it = 0; it < 2; it++) {
            int idx = tid + 256 * it;
            int row = idx >> 2;
            int q = idx & 3;
            int gr = rowBase + row;
            if (gr < M) {
                const float* src = Af + (size_t)gr * KD + k0 + 8 * q;
                pa[it][0] = *reinterpret_cast<const float4*>(src);
                pa[it][1] = *reinterpret_cast<const float4*>(src + 4);
            } else {
                pa[it][0] = make_float4(0.f, 0.f, 0.f, 0.f);
                pa[it][1] = make_float4(0.f, 0.f, 0.f, 0.f);
            }
        }
    };
    auto stsA = [&](int stage) {
        #pragma unroll
        for (int it = 0; it < 2; it++) {
            int idx = tid + 256 * it;
            int row = idx >> 2;
            int q = idx & 3;
            uint4 u;
            u.x = h2u(__floats2half2_rn(pa[it][0].x, pa[it][0].y));
            u.y = h2u(__floats2half2_rn(pa[it][0].z, pa[it][0].w));
            u.z = h2u(__floats2half2_rn(pa[it][1].x, pa[it][1].y));
            u.w = h2u(__floats2half2_rn(pa[it][1].z, pa[it][1].w));
            *reinterpret_cast<uint4*>(&As[stage][row][8 * q]) = u;
        }
    };
    auto cpA = [&](int stage, int k0) {
        #pragma unroll
        for (int it = 0; it < 2; it++) {
            int idx = tid + 256 * it;
            int row = idx >> 2;
            int q = idx & 3;
            int gr = rowBase + row;
            cp_async16(&As[stage][row][8 * q],
                       Ah + (size_t)gr * KD + k0 + 8 * q, gr < M);
        }
    };

    if (CONVA) { ldgA(0); loadB(0, 0); }
    else       { cpA(0, 0); loadB(0, 0); }

    int g = lane >> 3;       // ldmatrix lane group 0..3
    int gl = lane & 7;

    for (int t = 0; t < T; t++) {
        int st = t & 1;
        if (CONVA) {
            stsA(st);
            if (t + 1 < T) { ldgA((t + 1) * BK); loadB(st ^ 1, (t + 1) * BK); cp_wait<1>(); }
            else cp_wait<0>();
        } else {
            if (t + 1 < T) { cpA(st ^ 1, (t + 1) * BK); loadB(st ^ 1, (t + 1) * BK); cp_wait<1>(); }
            else cp_wait<0>();
        }
        __syncthreads();

        #pragma unroll
        for (int kk = 0; kk < 2; kk++) {
            int kb = 16 * kk;
            uint32_t af[MT][4];
            #pragma unroll
            for (int mt = 0; mt < MT; mt++) {
                // groups: g0 rows r+0..7 @kb, g1 rows r+8..15 @kb, g2 rows+0..7 @kb+8, g3 rows+8..15 @kb+8
                int row = wm * 64 + mt * 16 + ((g & 1) << 3) + gl;
                int colh = kb + ((g >> 1) << 3);
                uint32_t addr = (uint32_t)__cvta_generic_to_shared(&As[st][row][colh]);
                ldsm_x4(af[mt][0], af[mt][1], af[mt][2], af[mt][3], addr);
            }
            uint32_t bf[NT][2];
            #pragma unroll
            for (int ntp = 0; ntp < NT / 2; ntp++) {
                // g0: n+0..7 @kb -> bf[2p][0]; g1: n+0..7 @kb+8 -> bf[2p][1];
                // g2: n+8..15 @kb -> bf[2p+1][0]; g3: n+8..15 @kb+8 -> bf[2p+1][1]
                int n = wn * WN + ntp * 16 + ((g >> 1) << 3) + gl;
                int colh = kb + ((g & 1) << 3);
                uint32_t addr = (uint32_t)__cvta_generic_to_shared(&Bs[st][n][colh]);
                ldsm_x4(bf[2 * ntp][0], bf[2 * ntp][1], bf[2 * ntp + 1][0], bf[2 * ntp + 1][1], addr);
            }
            #pragma unroll
            for (int mt = 0; mt < MT; mt++)
                #pragma unroll
                for (int nt = 0; nt < NT; nt++) {
                    asm volatile(
                        "mma.sync.aligned.m16n8k16.row.col.f32.f16.f16.f32 "
                        "{%0,%1,%2,%3}, {%4,%5,%6,%7}, {%8,%9}, {%0,%1,%2,%3};"
                        : "+f"(acc[mt][nt][0]), "+f"(acc[mt][nt][1]),
                          "+f"(acc[mt][nt][2]), "+f"(acc[mt][nt][3])
                        : "r"(af[mt][0]), "r"(af[mt][1]), "r"(af[mt][2]), "r"(af[mt][3]),
                          "r"(bf[nt][0]), "r"(bf[nt][1]));
                }
        }
        __syncthreads();
    }

    // epilogue: dot-reduction buffer overlays smem
    float* sred = reinterpret_cast<float*>(&As[0][0][0]);  // [2][BM]
    for (int t = tid; t < 2 * BM; t += 256) sred[t] = 0.f;
    __syncthreads();

    #pragma unroll
    for (int mt = 0; mt < MT; mt++) {
        int rl = wm * 64 + mt * 16 + (lane >> 2);
        int r0 = rowBase + rl;
        float s_lo = 0.f, d_lo = 0.f, s_hi = 0.f, d_hi = 0.f;
        #pragma unroll
        for (int nt = 0; nt < NT; nt++) {
            int col = wn * WN + nt * 8 + 2 * (lane & 3);
            float a0 = asrc[col], a1 = asrc[col + 1];
            float e0 = adst[col], e1 = adst[col + 1];
            s_lo += acc[mt][nt][0] * a0 + acc[mt][nt][1] * a1;
            d_lo += acc[mt][nt][0] * e0 + acc[mt][nt][1] * e1;
            s_hi += acc[mt][nt][2] * a0 + acc[mt][nt][3] * a1;
            d_hi += acc[mt][nt][2] * e0 + acc[mt][nt][3] * e1;
            if (r0 < M)
                *reinterpret_cast<__half2*>(Cmat + (size_t)r0 * BN + col) =
                    __floats2half2_rn(acc[mt][nt][0], acc[mt][nt][1]);
            if (r0 + 8 < M)
                *reinterpret_cast<__half2*>(Cmat + (size_t)(r0 + 8) * BN + col) =
                    __floats2half2_rn(acc[mt][nt][2], acc[mt][nt][3]);
        }
        #pragma unroll
        for (int o = 1; o <= 2; o <<= 1) {
            s_lo += __shfl_xor_sync(0xffffffffu, s_lo, o);
            d_lo += __shfl_xor_sync(0xffffffffu, d_lo, o);
            s_hi += __shfl_xor_sync(0xffffffffu, s_hi, o);
            d_hi += __shfl_xor_sync(0xffffffffu, d_hi, o);
        }
        if ((lane & 3) == 0) {
            atomicAdd(&sred[rl], s_lo);
            atomicAdd(&sred[BM + rl], d_lo);
            atomicAdd(&sred[rl + 8], s_hi);
            atomicAdd(&sred[BM + rl + 8], d_hi);
        }
    }
    __syncthreads();
    for (int t = tid; t < BM; t += 256) {
        int gr = rowBase + t;
        if (gr < M) { sv[gr] = sred[t]; dv[gr] = sred[BM + t]; }
    }
}

// ---------------- aggregation (fp16 gather): out = act(softmax-sum + b) ----------------
template <int F, int ACT, bool OUTH>
__global__ __launch_bounds__(256) void aggregate_kernel(
        const __half* __restrict__ h, const float* __restrict__ sv,
        const float* __restrict__ dv, const int* __restrict__ rowptr,
        const int* __restrict__ colidx, const float* __restrict__ bias,
        void* __restrict__ outp, int n) {
    constexpr int V = F / 32;
    int warp = (blockIdx.x * blockDim.x + threadIdx.x) >> 5;
    int lane = threadIdx.x & 31;
    if (warp >= n) return;
    int i = warp;
    int start = rowptr[i], end = rowptr[i + 1];
    int len = end - start;
    float di = dv[i];

    float a0 = 0.f, a1 = 0.f, a2 = 0.f, a3 = 0.f;
    float Z = 0.f;

    auto accum = [&](int s, float w) {
        if (V == 4) {
            uint2 u = *reinterpret_cast<const uint2*>(h + (size_t)s * F + 4 * lane);
            float2 f01 = __half22float2(*reinterpret_cast<__half2*>(&u.x));
            float2 f23 = __half22float2(*reinterpret_cast<__half2*>(&u.y));
            a0 += w * f01.x; a1 += w * f01.y; a2 += w * f23.x; a3 += w * f23.y;
        } else {
            __half2 u = *reinterpret_cast<const __half2*>(h + (size_t)s * F + 2 * lane);
            float2 f01 = __half22float2(u);
            a0 += w * f01.x; a1 += w * f01.y;
        }
    };
    auto bcast4 = [&](int sn, float w, int t, int cnt) {
        int tt = t;
        for (; tt + 4 <= cnt; tt += 4) {
            int s0 = __shfl_sync(0xffffffffu, sn, tt);
            int s1 = __shfl_sync(0xffffffffu, sn, tt + 1);
            int s2 = __shfl_sync(0xffffffffu, sn, tt + 2);
            int s3 = __shfl_sync(0xffffffffu, sn, tt + 3);
            float w0 = __shfl_sync(0xffffffffu, w, tt);
            float w1 = __shfl_sync(0xffffffffu, w, tt + 1);
            float w2 = __shfl_sync(0xffffffffu, w, tt + 2);
            float w3 = __shfl_sync(0xffffffffu, w, tt + 3);
            accum(s0, w0); accum(s1, w1); accum(s2, w2); accum(s3, w3);
        }
        for (; tt < cnt; tt++) {
            int sb = __shfl_sync(0xffffffffu, sn, tt);
            float wb = __shfl_sync(0xffffffffu, w, tt);
            accum(sb, wb);
        }
    };

    if (len <= 32) {
        // fast path: single chunk — gather logits ONCE, max/exp/sum from registers
        int sn = 0;
        float x = -INFINITY;
        if (lane < len) {
            sn = colidx[start + lane];
            float xx = sv[sn] + di;
            x = (xx > 0.f) ? xx : 0.2f * xx;
        }
        float m = x;
        #pragma unroll
        for (int o = 16; o; o >>= 1) m = fmaxf(m, __shfl_xor_sync(0xffffffffu, m, o));
        float w = (lane < len) ? __expf(x - m) : 0.f;
        Z = w;
        #pragma unroll
        for (int o = 16; o; o >>= 1) Z += __shfl_xor_sync(0xffffffffu, Z, o);
        bcast4(sn, w, 0, len);
    } else {
        // general path: two passes
        float m = -INFINITY;
        for (int j = start + lane; j < end; j += 32) {
            float x = sv[colidx[j]] + di;
            x = (x > 0.f) ? x : 0.2f * x;
            m = fmaxf(m, x);
        }
        #pragma unroll
        for (int o = 16; o; o >>= 1) m = fmaxf(m, __shfl_xor_sync(0xffffffffu, m, o));

        for (int j0 = start; j0 < end; j0 += 32) {
            int j = j0 + lane;
            int sn = 0;
            float w = 0.f;
            if (j < end) {
                sn = colidx[j];
                float x = sv[sn] + di;
                x = (x > 0.f) ? x : 0.2f * x;
                w = __expf(x - m);
                Z += w;
            }
            bcast4(sn, w, 0, min(32, end - j0));
        }
        #pragma unroll
        for (int o = 16; o; o >>= 1) Z += __shfl_xor_sync(0xffffffffu, Z, o);
    }

    float invZ = 1.f / (Z + 1e-16f);
    float r0, r1, r2 = 0.f, r3 = 0.f;
    if (V == 4) {
        float4 bb = *reinterpret_cast<const float4*>(bias + 4 * lane);
        r0 = a0 * invZ + bb.x; r1 = a1 * invZ + bb.y;
        r2 = a2 * invZ + bb.z; r3 = a3 * invZ + bb.w;
    } else {
        float2 bb = *reinterpret_cast<const float2*>(bias + 2 * lane);
        r0 = a0 * invZ + bb.x; r1 = a1 * invZ + bb.y;
    }
    if (ACT == 0) {
        r0 = fmaxf(r0, 0.f); r1 = fmaxf(r1, 0.f);
        r2 = fmaxf(r2, 0.f); r3 = fmaxf(r3, 0.f);
    } else {
        r0 = 1.f / (1.f + __expf(-r0)); r1 = 1.f / (1.f + __expf(-r1));
        r2 = 1.f / (1.f + __expf(-r2)); r3 = 1.f / (1.f + __expf(-r3));
    }

    if (OUTH) {
        __half* out = (__half*)outp;
        if (V == 4) {
            uint2 u;
            u.x = h2u(__floats2half2_rn(r0, r1));
            u.y = h2u(__floats2half2_rn(r2, r3));
            *reinterpret_cast<uint2*>(out + (size_t)i * F + 4 * lane) = u;
        } else {
            *reinterpret_cast<__half2*>(out + (size_t)i * F + 2 * lane) =
                __floats2half2_rn(r0, r1);
        }
    } else {
        float* out = (float*)outp;
        if (V == 4)
            *reinterpret_cast<float4*>(out + (size_t)i * F + 4 * lane) =
                make_float4(r0, r1, r2, r3);
        else
            *reinterpret_cast<float2*>(out + (size_t)i * F + 2 * lane) =
                make_float2(r0, r1);
    }
}

// ---------------- host launch ----------------
static inline int cdiv(int a, int b) { return (a + b - 1) / b; }

extern "C" void kernel_launch(void* const* d_in, const int* in_sizes, int n_in,
                              void* d_out, int out_size) {
    const int*   ei    = (const int*)d_in[0];
    const float* embed = (const float*)d_in[1];
    const float* W1    = (const float*)d_in[2];
    const float* as1   = (const float*)d_in[3];
    const float* ad1   = (const float*)d_in[4];
    const float* b1    = (const float*)d_in[5];
    const float* W2    = (const float*)d_in[6];
    const float* as2   = (const float*)d_in[7];
    const float* ad2   = (const float*)d_in[8];
    const float* b2    = (const float*)d_in[9];

    int E = in_sizes[0] / 2;
    int N = in_sizes[1] / CDIM;
    const int* srcv = ei;
    const int* dstv = ei + E;

    void* p;
    cudaGetSymbolAddress(&p, g_deg);    int* deg    = (int*)p;
    cudaGetSymbolAddress(&p, g_incl);   int* incl   = (int*)p;
    cudaGetSymbolAddress(&p, g_bsums);  int* bsums  = (int*)p;
    cudaGetSymbolAddress(&p, g_rowptr); int* rowptr = (int*)p;
    cudaGetSymbolAddress(&p, g_pos);    int* pos    = (int*)p;
    cudaGetSymbolAddress(&p, g_col);    int* col    = (int*)p;
    cudaGetSymbolAddress(&p, g_h1);     __half* h1  = (__half*)p;
    cudaGetSymbolAddress(&p, g_x1);     __half* x1  = (__half*)p;
    cudaGetSymbolAddress(&p, g_h2);     __half* h2  = (__half*)p;
    cudaGetSymbolAddress(&p, g_w1t);    __half* w1t = (__half*)p;
    cudaGetSymbolAddress(&p, g_w2t);    __half* w2t = (__half*)p;
    cudaGetSymbolAddress(&p, g_s1);     float* s1   = (float*)p;
    cudaGetSymbolAddress(&p, g_d1);     float* d1   = (float*)p;
    cudaGetSymbolAddress(&p, g_s2);     float* s2   = (float*)p;
    cudaGetSymbolAddress(&p, g_d2);     float* d2   = (float*)p;
    float* out = (float*)d_out;

    int nb = cdiv(N, 1024);

    wtrans_kernel<CDIM, HDIM><<<cdiv(CDIM * HDIM, 256), 256>>>(W1, w1t);
    init_deg_kernel<<<cdiv(N, 256), 256>>>(deg, N);
    hist_kernel<<<cdiv(E, 256), 256>>>(dstv, deg, E);
    mma_gemm_kernel<HDIM, CDIM, true><<<cdiv(N, 128), 256>>>(embed, w1t, h1, as1, ad1, s1, d1, N);
    wtrans_kernel<HDIM, KOUT><<<cdiv(HDIM * KOUT, 256), 256>>>(W2, w2t);
    scan_block_kernel<<<nb, 1024>>>(deg, incl, bsums, N);
    scan_bsums_kernel<<<1, 128>>>(bsums, nb);
    finalize_rowptr_kernel<<<cdiv(N + 1, 256), 256>>>(incl, bsums, deg, rowptr, pos, N);
    scatter_kernel<<<cdiv(E + N, 256), 256>>>(srcv, dstv, pos, col, E, N);

    aggregate_kernel<HDIM, 0, true><<<cdiv(N, 8), 256>>>(h1, s1, d1, rowptr, col, b1, x1, N);

    mma_gemm_kernel<KOUT, HDIM, false><<<cdiv(N, 128), 256>>>(x1, w2t, h2, as2, ad2, s2, d2, N);
    aggregate_kernel<KOUT, 1, false><<<cdiv(N, 8), 256>>>(h2, s2, d2, rowptr, col, b2, out, N);
}

// round 8
// speedup vs baseline: 1.7181x; 1.0387x over previous
#include <cuda_runtime.h>
#include <cuda_fp16.h>
#include <math.h>
#include <stdint.h>

// Problem-fixed shapes: N=100000, C=256, H=128, K=64, E=1600000
#define NN   100000
#define EE   1600000
#define ETOT (EE + NN)
#define CDIM 256
#define HDIM 128
#define KOUT 64

// ---------------- device scratch (static, no allocation) ----------------
__device__ int    g_deg[NN];
__device__ int    g_incl[NN];
__device__ int    g_bsums[256];
__device__ int    g_rowptr[NN + 1];
__device__ int    g_pos[NN];
__device__ int    g_col[ETOT];
__device__ __half g_h1[NN * HDIM];
__device__ __half g_x1[NN * HDIM];
__device__ __half g_h2[NN * KOUT];
__device__ __half g_w1t[HDIM * CDIM];
__device__ __half g_w2t[KOUT * HDIM];
__device__ float  g_s1[NN], g_d1[NN], g_s2[NN], g_d2[NN];

// ---------------- weight transpose + fp16 convert: WT[n][k] = W[k][n] ----------------
template <int KD, int BN>
__global__ void wtrans_kernel(const float* __restrict__ W, __half* __restrict__ WT) {
    int idx = blockIdx.x * blockDim.x + threadIdx.x;
    if (idx < KD * BN) {
        int n = idx / KD, k = idx % KD;
        WT[idx] = __float2half(W[(size_t)k * BN + n]);
    }
}

// ---------------- CSR build ----------------
__global__ void init_deg_kernel(int* deg, int n) {
    int i = blockIdx.x * blockDim.x + threadIdx.x;
    if (i < n) deg[i] = 1;  // self-loop
}

__global__ void hist_kernel(const int* __restrict__ dst, int* deg, int e) {
    int i = blockIdx.x * blockDim.x + threadIdx.x;
    if (i < e) atomicAdd(&deg[dst[i]], 1);
}

__global__ void scan_block_kernel(const int* __restrict__ deg, int* incl, int* bsums, int n) {
    __shared__ int sh[1024];
    int t = threadIdx.x;
    int gid = blockIdx.x * 1024 + t;
    sh[t] = (gid < n) ? deg[gid] : 0;
    __syncthreads();
    #pragma unroll
    for (int off = 1; off < 1024; off <<= 1) {
        int v = (t >= off) ? sh[t - off] : 0;
        __syncthreads();
        sh[t] += v;
        __syncthreads();
    }
    if (gid < n) incl[gid] = sh[t];
    if (t == 1023) bsums[blockIdx.x] = sh[t];
}

__global__ void scan_bsums_kernel(int* bsums, int nb) {
    __shared__ int sh[128];
    int t = threadIdx.x;
    sh[t] = (t < nb) ? bsums[t] : 0;
    __syncthreads();
    #pragma unroll
    for (int off = 1; off < 128; off <<= 1) {
        int v = (t >= off) ? sh[t - off] : 0;
        __syncthreads();
        sh[t] += v;
        __syncthreads();
    }
    if (t < nb) bsums[t] = (t == 0) ? 0 : sh[t - 1];
}

__global__ void finalize_rowptr_kernel(const int* __restrict__ incl, const int* __restrict__ bsums,
                                       const int* __restrict__ deg, int* rowptr, int* pos, int n) {
    int gid = blockIdx.x * blockDim.x + threadIdx.x;
    if (gid < n) {
        int v = incl[gid] + bsums[gid >> 10];
        rowptr[gid + 1] = v;
        pos[gid] = v - deg[gid];
    }
    if (gid == 0) rowptr[0] = 0;
}

__global__ void scatter_kernel(const int* __restrict__ srcv, const int* __restrict__ dstv,
                               int* pos, int* colv, int e, int n) {
    int i = blockIdx.x * blockDim.x + threadIdx.x;
    if (i < e) {
        int p = atomicAdd(&pos[dstv[i]], 1);
        colv[p] = srcv[i];
    } else if (i < e + n) {
        int v = i - e;
        int p = atomicAdd(&pos[v], 1);
        colv[p] = v;
    }
}

// ---------------- asm helpers ----------------
__device__ __forceinline__ void cp_async16(void* smem_dst, const void* gmem_src, bool pred) {
    uint32_t saddr = (uint32_t)__cvta_generic_to_shared(smem_dst);
    int sz = pred ? 16 : 0;
    asm volatile("cp.async.cg.shared.global [%0], [%1], 16, %2;\n"
                 :: "r"(saddr), "l"(gmem_src), "r"(sz));
}
__device__ __forceinline__ void cp_commit() {
    asm volatile("cp.async.commit_group;\n");
}
template <int N>
__device__ __forceinline__ void cp_wait() {
    asm volatile("cp.async.wait_group %0;\n" :: "n"(N));
}
__device__ __forceinline__ uint32_t h2u(__half2 h) { return *reinterpret_cast<uint32_t*>(&h); }
__device__ __forceinline__ void ldsm_x4(uint32_t& r0, uint32_t& r1, uint32_t& r2, uint32_t& r3,
                                        uint32_t addr) {
    asm volatile("ldmatrix.sync.aligned.m8n8.x4.shared.b16 {%0,%1,%2,%3}, [%4];"
                 : "=r"(r0), "=r"(r1), "=r"(r2), "=r"(r3) : "r"(addr));
}

// ---------------- fp16 GEMM (m16n8k16): B fully preloaded, A 2-stage ----------------
// C(half)[M x BN] = A[M x KD] * BT^T (BT [BN][KD] fp16). Fused sv/dv dots.
template <int BN, int KD, bool CONVA>
__global__ __launch_bounds__(256) void mma_gemm_kernel(const void* __restrict__ Ap,
                                                       const __half* __restrict__ BT,
                                                       __half* __restrict__ Cmat,
                                                       const float* __restrict__ asrc,
                                                       const float* __restrict__ adst,
                                                       float* __restrict__ sv,
                                                       float* __restrict__ dv, int M) {
    constexpr int BM = 128, BK = 32;
    constexpr int WN = BN / 4;
    constexpr int MT = 4;
    constexpr int NT = WN / 8;
    constexpr int ST  = 40;        // A row stride (halves)
    constexpr int ST2 = KD + 8;    // B row stride (halves): banks 4n%32, conflict-free
    constexpr int T = KD / BK;

    extern __shared__ __half sm[];
    __half* As = sm;                      // [2][BM][ST]
    __half* Bf = sm + 2 * BM * ST;        // [BN][ST2]

    int tid = threadIdx.x;
    int lane = tid & 31;
    int wid = tid >> 5;
    int wm = wid & 1;
    int wn = wid >> 1;
    int rowBase = blockIdx.x * BM;

    const float*  Af = (const float*)Ap;
    const __half* Ah = (const __half*)Ap;

    float acc[MT][NT][4];
    #pragma unroll
    for (int i = 0; i < MT; i++)
        #pragma unroll
        for (int j = 0; j < NT; j++)
            #pragma unroll
            for (int r = 0; r < 4; r++) acc[i][j][r] = 0.f;

    // prologue: B full tile via one cp.async group
    {
        constexpr int QR = KD / 8;                 // 16B chunks per B row
        constexpr int CH = BN * QR;
        constexpr int BIT = CH / 256;
        #pragma unroll
        for (int it = 0; it < BIT; it++) {
            int idx = tid + 256 * it;
            int n = idx / QR;
            int q = idx % QR;
            cp_async16(&Bf[n * ST2 + 8 * q], BT + (size_t)n * KD + 8 * q, true);
        }
        cp_commit();
    }

    float4 pa[2][2];
    auto ldgA = [&](int k0) {
        #pragma unroll
        for (int it = 0; it < 2; it++) {
            int idx = tid + 256 * it;
            int row = idx >> 2;
            int q = idx & 3;
            int gr = rowBase + row;
            if (gr < M) {
                const float* src = Af + (size_t)gr * KD + k0 + 8 * q;
                pa[it][0] = *reinterpret_cast<const float4*>(src);
                pa[it][1] = *reinterpret_cast<const float4*>(src + 4);
            } else {
                pa[it][0] = make_float4(0.f, 0.f, 0.f, 0.f);
                pa[it][1] = make_float4(0.f, 0.f, 0.f, 0.f);
            }
        }
    };
    auto stsA = [&](int stage) {
        #pragma unroll
        for (int it = 0; it < 2; it++) {
            int idx = tid + 256 * it;
            int row = idx >> 2;
            int q = idx & 3;
            uint4 u;
            u.x = h2u(__floats2half2_rn(pa[it][0].x, pa[it][0].y));
            u.y = h2u(__floats2half2_rn(pa[it][0].z, pa[it][0].w));
            u.z = h2u(__floats2half2_rn(pa[it][1].x, pa[it][1].y));
            u.w = h2u(__floats2half2_rn(pa[it][1].z, pa[it][1].w));
            *reinterpret_cast<uint4*>(&As[(stage * BM + row) * ST + 8 * q]) = u;
        }
    };
    auto cpA = [&](int stage, int k0) {
        #pragma unroll
        for (int it = 0; it < 2; it++) {
            int idx = tid + 256 * it;
            int row = idx >> 2;
            int q = idx & 3;
            int gr = rowBase + row;
            cp_async16(&As[(stage * BM + row) * ST + 8 * q],
                       Ah + (size_t)gr * KD + k0 + 8 * q, gr < M);
        }
        cp_commit();
    };

    if (CONVA) ldgA(0);
    else       cpA(0, 0);

    int g = lane >> 3;
    int gl = lane & 7;

    for (int t = 0; t < T; t++) {
        int st = t & 1;
        if (CONVA) {
            stsA(st);
            if (t + 1 < T) ldgA((t + 1) * BK);
            if (t == 0) cp_wait<0>();              // B resident from here on
        } else {
            if (t + 1 < T) { cpA(st ^ 1, (t + 1) * BK); cp_wait<1>(); }
            else cp_wait<0>();
        }
        __syncthreads();

        #pragma unroll
        for (int kk = 0; kk < 2; kk++) {
            int kglob = t * BK + 16 * kk;
            uint32_t af[MT][4];
            #pragma unroll
            for (int mt = 0; mt < MT; mt++) {
                int row = wm * 64 + mt * 16 + ((g & 1) << 3) + gl;
                int colh = 16 * kk + ((g >> 1) << 3);
                uint32_t addr = (uint32_t)__cvta_generic_to_shared(
                    &As[(st * BM + row) * ST + colh]);
                ldsm_x4(af[mt][0], af[mt][1], af[mt][2], af[mt][3], addr);
            }
            uint32_t bf[NT][2];
            #pragma unroll
            for (int ntp = 0; ntp < NT / 2; ntp++) {
                int n = wn * WN + ntp * 16 + ((g >> 1) << 3) + gl;
                int colh = kglob + ((g & 1) << 3);
                uint32_t addr = (uint32_t)__cvta_generic_to_shared(&Bf[n * ST2 + colh]);
                ldsm_x4(bf[2 * ntp][0], bf[2 * ntp][1], bf[2 * ntp + 1][0], bf[2 * ntp + 1][1], addr);
            }
            #pragma unroll
            for (int mt = 0; mt < MT; mt++)
                #pragma unroll
                for (int nt = 0; nt < NT; nt++) {
                    asm volatile(
                        "mma.sync.aligned.m16n8k16.row.col.f32.f16.f16.f32 "
                        "{%0,%1,%2,%3}, {%4,%5,%6,%7}, {%8,%9}, {%0,%1,%2,%3};"
                        : "+f"(acc[mt][nt][0]), "+f"(acc[mt][nt][1]),
                          "+f"(acc[mt][nt][2]), "+f"(acc[mt][nt][3])
                        : "r"(af[mt][0]), "r"(af[mt][1]), "r"(af[mt][2]), "r"(af[mt][3]),
                          "r"(bf[nt][0]), "r"(bf[nt][1]));
                }
        }
        __syncthreads();
    }

    // epilogue: dot-reduction buffer overlays A smem
    float* sred = reinterpret_cast<float*>(As);  // [2][BM]
    for (int t = tid; t < 2 * BM; t += 256) sred[t] = 0.f;
    __syncthreads();

    #pragma unroll
    for (int mt = 0; mt < MT; mt++) {
        int rl = wm * 64 + mt * 16 + (lane >> 2);
        int r0 = rowBase + rl;
        float s_lo = 0.f, d_lo = 0.f, s_hi = 0.f, d_hi = 0.f;
        #pragma unroll
        for (int nt = 0; nt < NT; nt++) {
            int col = wn * WN + nt * 8 + 2 * (lane & 3);
            float a0 = asrc[col], a1 = asrc[col + 1];
            float e0 = adst[col], e1 = adst[col + 1];
            s_lo += acc[mt][nt][0] * a0 + acc[mt][nt][1] * a1;
            d_lo += acc[mt][nt][0] * e0 + acc[mt][nt][1] * e1;
            s_hi += acc[mt][nt][2] * a0 + acc[mt][nt][3] * a1;
            d_hi += acc[mt][nt][2] * e0 + acc[mt][nt][3] * e1;
            if (r0 < M)
                *reinterpret_cast<__half2*>(Cmat + (size_t)r0 * BN + col) =
                    __floats2half2_rn(acc[mt][nt][0], acc[mt][nt][1]);
            if (r0 + 8 < M)
                *reinterpret_cast<__half2*>(Cmat + (size_t)(r0 + 8) * BN + col) =
                    __floats2half2_rn(acc[mt][nt][2], acc[mt][nt][3]);
        }
        #pragma unroll
        for (int o = 1; o <= 2; o <<= 1) {
            s_lo += __shfl_xor_sync(0xffffffffu, s_lo, o);
            d_lo += __shfl_xor_sync(0xffffffffu, d_lo, o);
            s_hi += __shfl_xor_sync(0xffffffffu, s_hi, o);
            d_hi += __shfl_xor_sync(0xffffffffu, d_hi, o);
        }
        if ((lane & 3) == 0) {
            atomicAdd(&sred[rl], s_lo);
            atomicAdd(&sred[BM + rl], d_lo);
            atomicAdd(&sred[rl + 8], s_hi);
            atomicAdd(&sred[BM + rl + 8], d_hi);
        }
    }
    __syncthreads();
    for (int t = tid; t < BM; t += 256) {
        int gr = rowBase + t;
        if (gr < M) { sv[gr] = sred[t]; dv[gr] = sred[BM + t]; }
    }
}

// ---------------- aggregation (fp16 gather): out = act(softmax-sum + b) ----------------
template <int F, int ACT, bool OUTH>
__global__ __launch_bounds__(256) void aggregate_kernel(
        const __half* __restrict__ h, const float* __restrict__ sv,
        const float* __restrict__ dv, const int* __restrict__ rowptr,
        const int* __restrict__ colidx, const float* __restrict__ bias,
        void* __restrict__ outp, int n) {
    constexpr int V = F / 32;
    int warp = (blockIdx.x * blockDim.x + threadIdx.x) >> 5;
    int lane = threadIdx.x & 31;
    if (warp >= n) return;
    int i = warp;
    int start = rowptr[i], end = rowptr[i + 1];
    int len = end - start;
    float di = dv[i];

    float a0 = 0.f, a1 = 0.f, a2 = 0.f, a3 = 0.f;
    float Z = 0.f;

    auto accum = [&](int s, float w) {
        if (V == 4) {
            uint2 u = *reinterpret_cast<const uint2*>(h + (size_t)s * F + 4 * lane);
            float2 f01 = __half22float2(*reinterpret_cast<__half2*>(&u.x));
            float2 f23 = __half22float2(*reinterpret_cast<__half2*>(&u.y));
            a0 += w * f01.x; a1 += w * f01.y; a2 += w * f23.x; a3 += w * f23.y;
        } else {
            __half2 u = *reinterpret_cast<const __half2*>(h + (size_t)s * F + 2 * lane);
            float2 f01 = __half22float2(u);
            a0 += w * f01.x; a1 += w * f01.y;
        }
    };
    auto bcast4 = [&](int sn, float w, int cnt) {
        int tt = 0;
        for (; tt + 4 <= cnt; tt += 4) {
            int s0 = __shfl_sync(0xffffffffu, sn, tt);
            int s1 = __shfl_sync(0xffffffffu, sn, tt + 1);
            int s2 = __shfl_sync(0xffffffffu, sn, tt + 2);
            int s3 = __shfl_sync(0xffffffffu, sn, tt + 3);
            float w0 = __shfl_sync(0xffffffffu, w, tt);
            float w1 = __shfl_sync(0xffffffffu, w, tt + 1);
            float w2 = __shfl_sync(0xffffffffu, w, tt + 2);
            float w3 = __shfl_sync(0xffffffffu, w, tt + 3);
            accum(s0, w0); accum(s1, w1); accum(s2, w2); accum(s3, w3);
        }
        for (; tt < cnt; tt++) {
            int sb = __shfl_sync(0xffffffffu, sn, tt);
            float wb = __shfl_sync(0xffffffffu, w, tt);
            accum(sb, wb);
        }
    };

    if (len <= 32) {
        int sn = 0;
        float x = -INFINITY;
        if (lane < len) {
            sn = colidx[start + lane];
            float xx = sv[sn] + di;
            x = (xx > 0.f) ? xx : 0.2f * xx;
        }
        float m = x;
        #pragma unroll
        for (int o = 16; o; o >>= 1) m = fmaxf(m, __shfl_xor_sync(0xffffffffu, m, o));
        float w = (lane < len) ? __expf(x - m) : 0.f;
        Z = w;
        #pragma unroll
        for (int o = 16; o; o >>= 1) Z += __shfl_xor_sync(0xffffffffu, Z, o);
        bcast4(sn, w, len);
    } else {
        float m = -INFINITY;
        for (int j = start + lane; j < end; j += 32) {
            float x = sv[colidx[j]] + di;
            x = (x > 0.f) ? x : 0.2f * x;
            m = fmaxf(m, x);
        }
        #pragma unroll
        for (int o = 16; o; o >>= 1) m = fmaxf(m, __shfl_xor_sync(0xffffffffu, m, o));

        for (int j0 = start; j0 < end; j0 += 32) {
            int j = j0 + lane;
            int sn = 0;
            float w = 0.f;
            if (j < end) {
                sn = colidx[j];
                float x = sv[sn] + di;
                x = (x > 0.f) ? x : 0.2f * x;
                w = __expf(x - m);
                Z += w;
            }
            bcast4(sn, w, min(32, end - j0));
        }
        #pragma unroll
        for (int o = 16; o; o >>= 1) Z += __shfl_xor_sync(0xffffffffu, Z, o);
    }

    float invZ = 1.f / (Z + 1e-16f);
    float r0, r1, r2 = 0.f, r3 = 0.f;
    if (V == 4) {
        float4 bb = *reinterpret_cast<const float4*>(bias + 4 * lane);
        r0 = a0 * invZ + bb.x; r1 = a1 * invZ + bb.y;
        r2 = a2 * invZ + bb.z; r3 = a3 * invZ + bb.w;
    } else {
        float2 bb = *reinterpret_cast<const float2*>(bias + 2 * lane);
        r0 = a0 * invZ + bb.x; r1 = a1 * invZ + bb.y;
    }
    if (ACT == 0) {
        r0 = fmaxf(r0, 0.f); r1 = fmaxf(r1, 0.f);
        r2 = fmaxf(r2, 0.f); r3 = fmaxf(r3, 0.f);
    } else {
        r0 = 1.f / (1.f + __expf(-r0)); r1 = 1.f / (1.f + __expf(-r1));
        r2 = 1.f / (1.f + __expf(-r2)); r3 = 1.f / (1.f + __expf(-r3));
    }

    if (OUTH) {
        __half* out = (__half*)outp;
        if (V == 4) {
            uint2 u;
            u.x = h2u(__floats2half2_rn(r0, r1));
            u.y = h2u(__floats2half2_rn(r2, r3));
            *reinterpret_cast<uint2*>(out + (size_t)i * F + 4 * lane) = u;
        } else {
            *reinterpret_cast<__half2*>(out + (size_t)i * F + 2 * lane) =
                __floats2half2_rn(r0, r1);
        }
    } else {
        float* out = (float*)outp;
        if (V == 4)
            *reinterpret_cast<float4*>(out + (size_t)i * F + 4 * lane) =
                make_float4(r0, r1, r2, r3);
        else
            *reinterpret_cast<float2*>(out + (size_t)i * F + 2 * lane) =
                make_float2(r0, r1);
    }
}

// ---------------- host launch ----------------
static inline int cdiv(int a, int b) { return (a + b - 1) / b; }

extern "C" void kernel_launch(void* const* d_in, const int* in_sizes, int n_in,
                              void* d_out, int out_size) {
    const int*   ei    = (const int*)d_in[0];
    const float* embed = (const float*)d_in[1];
    const float* W1    = (const float*)d_in[2];
    const float* as1   = (const float*)d_in[3];
    const float* ad1   = (const float*)d_in[4];
    const float* b1    = (const float*)d_in[5];
    const float* W2    = (const float*)d_in[6];
    const float* as2   = (const float*)d_in[7];
    const float* ad2   = (const float*)d_in[8];
    const float* b2    = (const float*)d_in[9];

    int E = in_sizes[0] / 2;
    int N = in_sizes[1] / CDIM;
    const int* srcv = ei;
    const int* dstv = ei + E;

    void* p;
    cudaGetSymbolAddress(&p, g_deg);    int* deg    = (int*)p;
    cudaGetSymbolAddress(&p, g_incl);   int* incl   = (int*)p;
    cudaGetSymbolAddress(&p, g_bsums);  int* bsums  = (int*)p;
    cudaGetSymbolAddress(&p, g_rowptr); int* rowptr = (int*)p;
    cudaGetSymbolAddress(&p, g_pos);    int* pos    = (int*)p;
    cudaGetSymbolAddress(&p, g_col);    int* col    = (int*)p;
    cudaGetSymbolAddress(&p, g_h1);     __half* h1  = (__half*)p;
    cudaGetSymbolAddress(&p, g_x1);     __half* x1  = (__half*)p;
    cudaGetSymbolAddress(&p, g_h2);     __half* h2  = (__half*)p;
    cudaGetSymbolAddress(&p, g_w1t);    __half* w1t = (__half*)p;
    cudaGetSymbolAddress(&p, g_w2t);    __half* w2t = (__half*)p;
    cudaGetSymbolAddress(&p, g_s1);     float* s1   = (float*)p;
    cudaGetSymbolAddress(&p, g_d1);     float* d1   = (float*)p;
    cudaGetSymbolAddress(&p, g_s2);     float* s2   = (float*)p;
    cudaGetSymbolAddress(&p, g_d2);     float* d2   = (float*)p;
    float* out = (float*)d_out;

    int nb = cdiv(N, 1024);

    // dynamic smem: A double-buffer + full B tile
    constexpr int SMEM1 = (2 * 128 * 40 + 128 * (CDIM + 8)) * 2;  // 88064
    constexpr int SMEM2 = (2 * 128 * 40 + 64 * (HDIM + 8)) * 2;   // 37888

    // lazy one-time setup (runs on the uncaptured correctness call)
    static cudaStream_t s_side = nullptr;
    static cudaEvent_t ev_fork = nullptr, ev_join = nullptr;
    if (!s_side) {
        cudaStreamCreateWithFlags(&s_side, cudaStreamNonBlocking);
        cudaEventCreateWithFlags(&ev_fork, cudaEventDisableTiming);
        cudaEventCreateWithFlags(&ev_join, cudaEventDisableTiming);
        cudaFuncSetAttribute(mma_gemm_kernel<HDIM, CDIM, true>,
                             cudaFuncAttributeMaxDynamicSharedMemorySize, SMEM1);
        cudaFuncSetAttribute(mma_gemm_kernel<KOUT, HDIM, false>,
                             cudaFuncAttributeMaxDynamicSharedMemorySize, SMEM2);
    }

    // main stream: weights + GEMM1 chain
    wtrans_kernel<CDIM, HDIM><<<cdiv(CDIM * HDIM, 256), 256>>>(W1, w1t);

    // fork: CSR build on side stream (depends only on edge_index)
    cudaEventRecord(ev_fork, 0);
    cudaStreamWaitEvent(s_side, ev_fork, 0);
    init_deg_kernel<<<cdiv(N, 256), 256, 0, s_side>>>(deg, N);
    hist_kernel<<<cdiv(E, 256), 256, 0, s_side>>>(dstv, deg, E);
    scan_block_kernel<<<nb, 1024, 0, s_side>>>(deg, incl, bsums, N);
    scan_bsums_kernel<<<1, 128, 0, s_side>>>(bsums, nb);
    finalize_rowptr_kernel<<<cdiv(N + 1, 256), 256, 0, s_side>>>(incl, bsums, deg, rowptr, pos, N);
    scatter_kernel<<<cdiv(E + N, 256), 256, 0, s_side>>>(srcv, dstv, pos, col, E, N);
    cudaEventRecord(ev_join, s_side);

    // main stream (overlapped with CSR): GEMM1 + W2 transpose
    mma_gemm_kernel<HDIM, CDIM, true><<<cdiv(N, 128), 256, SMEM1>>>(embed, w1t, h1, as1, ad1, s1, d1, N);
    wtrans_kernel<HDIM, KOUT><<<cdiv(HDIM * KOUT, 256), 256>>>(W2, w2t);

    // join: aggregation needs CSR + h1
    cudaStreamWaitEvent(0, ev_join, 0);
    aggregate_kernel<HDIM, 0, true><<<cdiv(N, 8), 256>>>(h1, s1, d1, rowptr, col, b1, x1, N);

    mma_gemm_kernel<KOUT, HDIM, false><<<cdiv(N, 128), 256, SMEM2>>>(x1, w2t, h2, as2, ad2, s2, d2, N);
    aggregate_kernel<KOUT, 1, false><<<cdiv(N, 8), 256>>>(h2, s2, d2, rowptr, col, b2, out, N);
}